// round 4
// baseline (speedup 1.0000x reference)
#include <cuda_runtime.h>

// Problem constants (fixed shapes from reference)
#define BB    256      // batch
#define SS    128      // sequence
#define DD    1024     // d_model
#define DQ    256      // d_model/4 (style hidden)
#define TXT   768      // caption dim
#define KTOT  1024     // DQ + TXT  (concat GEMM K)

// Scratch (device globals — no allocation allowed)
__device__ float g_A[BB * KTOT];     // [hidden(256) | captions(768)] per batch row
__device__ float g_comb[BB * DD];    // style_embed + page_embed + biases

// ---------------------------------------------------------------------------
// Kernel 1: build hidden = relu(style@W1 + b1), pack A = [hidden | cap],
//           and write the padding mask (types==0) as 0/1 floats.
// ---------------------------------------------------------------------------
__global__ void __launch_bounds__(256) prep_kernel(
    const int*   __restrict__ types,
    const float* __restrict__ style,   // [B,5]
    const float* __restrict__ cap,     // [B,768]
    const float* __restrict__ w1,      // [5,256]
    const float* __restrict__ b1,      // [256]
    float*       __restrict__ out_mask,
    int          write_mask)
{
    int idx = blockIdx.x * blockDim.x + threadIdx.x;
    if (idx < BB * KTOT) {
        int b = idx >> 10;
        int k = idx & (KTOT - 1);
        float v;
        if (k < DQ) {
            const float* srow = style + b * 5;
            float acc = b1[k];
            acc = fmaf(srow[0], w1[0 * DQ + k], acc);
            acc = fmaf(srow[1], w1[1 * DQ + k], acc);
            acc = fmaf(srow[2], w1[2 * DQ + k], acc);
            acc = fmaf(srow[3], w1[3 * DQ + k], acc);
            acc = fmaf(srow[4], w1[4 * DQ + k], acc);
            v = fmaxf(acc, 0.0f);
        } else {
            v = cap[b * TXT + (k - DQ)];
        }
        g_A[idx] = v;
    } else if (write_mask) {
        int m = idx - BB * KTOT;
        if (m < BB * SS) out_mask[m] = (types[m] == 0) ? 1.0f : 0.0f;
    }
}

// ---------------------------------------------------------------------------
// Kernel 2: g_comb[256,1024] = g_A[256,1024] @ [W2 ; Tw] + (b2 + tb)
// SGEMM: BM=32, BN=64, BK=16, 256 threads, 2x4 register tile.
// Grid: (1024/64, 256/32) = (16, 8) = 128 blocks.
// ---------------------------------------------------------------------------
__global__ void __launch_bounds__(256) gemm_kernel(
    const float* __restrict__ w2,   // [256,1024]
    const float* __restrict__ tw,   // [768,1024]
    const float* __restrict__ b2,   // [1024]
    const float* __restrict__ tb)   // [1024]
{
    __shared__ float  As[16][33];    // [k][m], padded to kill STS conflicts
    __shared__ float4 Bs[16][16];    // [k][n/4]

    const int tid = threadIdx.x;
    const int n0  = blockIdx.x * 64;
    const int m0  = blockIdx.y * 32;
    const int ty  = tid >> 4;        // 0..15 -> 2 rows each
    const int tx  = tid & 15;        // 0..15 -> 4 cols each

    float acc[2][4] = {};

    for (int k0 = 0; k0 < KTOT; k0 += 16) {
        // Load A tile (32x16): 2 elements per thread
        #pragma unroll
        for (int e = tid; e < 512; e += 256) {
            int row = e >> 4;
            int col = e & 15;
            As[col][row] = g_A[(m0 + row) * KTOT + k0 + col];
        }
        // Load B tile (16x64) from the concatenated weight: one float4/thread
        const float* Wp = (k0 < DQ) ? (w2 + k0 * DD) : (tw + (k0 - DQ) * DD);
        {
            int row = tid >> 4;
            int c4  = tid & 15;
            Bs[row][c4] = *reinterpret_cast<const float4*>(Wp + row * DD + n0 + c4 * 4);
        }
        __syncthreads();

        #pragma unroll
        for (int k = 0; k < 16; k++) {
            float  a0 = As[k][2 * ty];
            float  a1 = As[k][2 * ty + 1];
            float4 bv = Bs[k][tx];
            acc[0][0] = fmaf(a0, bv.x, acc[0][0]);
            acc[0][1] = fmaf(a0, bv.y, acc[0][1]);
            acc[0][2] = fmaf(a0, bv.z, acc[0][2]);
            acc[0][3] = fmaf(a0, bv.w, acc[0][3]);
            acc[1][0] = fmaf(a1, bv.x, acc[1][0]);
            acc[1][1] = fmaf(a1, bv.y, acc[1][1]);
            acc[1][2] = fmaf(a1, bv.z, acc[1][2]);
            acc[1][3] = fmaf(a1, bv.w, acc[1][3]);
        }
        __syncthreads();
    }

    const int n = n0 + tx * 4;
    float4 v2 = *reinterpret_cast<const float4*>(b2 + n);
    float4 vt = *reinterpret_cast<const float4*>(tb + n);
    float4 bias = make_float4(v2.x + vt.x, v2.y + vt.y, v2.z + vt.z, v2.w + vt.w);

    #pragma unroll
    for (int r = 0; r < 2; r++) {
        float4 o = make_float4(acc[r][0] + bias.x, acc[r][1] + bias.y,
                               acc[r][2] + bias.z, acc[r][3] + bias.w);
        *reinterpret_cast<float4*>(&g_comb[(m0 + 2 * ty + r) * DD + n]) = o;
    }
}

// ---------------------------------------------------------------------------
// Kernel 3: out[b,s,d] = type_emb[t] + pos_emb[idx] + final_pos[s]
//                        + (t==1) * comb[b]
// Block = 128 threads = one 128-float d-slab; loops 8 batches x 128 positions.
// pos_emb/final slab slices (64KB each) stay L1-resident -> DRAM-write bound.
// Grid: (256/8 batch-chunks, 1024/128 slabs) = (32, 8) = 256 blocks.
// ---------------------------------------------------------------------------
__global__ void __launch_bounds__(128) emb_kernel(
    const int*   __restrict__ types,
    const int*   __restrict__ inds,
    const float* __restrict__ temb,   // [5,1024]
    const float* __restrict__ pemb,   // [128,1024]
    const float* __restrict__ femb,   // [128,1024]
    float*       __restrict__ out)
{
    __shared__ int ts[SS];
    __shared__ int ix[SS];

    const int d  = blockIdx.y * 128 + threadIdx.x;
    const int b0 = blockIdx.x * 8;

    for (int bb = 0; bb < 8; bb++) {
        const int b = b0 + bb;
        __syncthreads();  // protect ts/ix from previous iteration readers
        ts[threadIdx.x] = types[b * SS + threadIdx.x];
        ix[threadIdx.x] = inds[b * SS + threadIdx.x];
        __syncthreads();

        const float comb = g_comb[b * DD + d];
        float* orow = out + (size_t)b * SS * DD + d;

        #pragma unroll 4
        for (int s = 0; s < SS; s++) {
            const int t = ts[s];
            float v = temb[t * DD + d] + pemb[ix[s] * DD + d] + femb[s * DD + d];
            if (t == 1) v += comb;
            orow[(size_t)s * DD] = v;
        }
    }
}

// ---------------------------------------------------------------------------
extern "C" void kernel_launch(void* const* d_in, const int* in_sizes, int n_in,
                              void* d_out, int out_size)
{
    const int*   types = (const int*)  d_in[0];   // element_types  [256,128] i32
    const int*   inds  = (const int*)  d_in[1];   // element_indices[256,128] i32
    const float* style = (const float*)d_in[2];   // [256,5]
    const float* cap   = (const float*)d_in[3];   // [256,768]
    const float* temb  = (const float*)d_in[4];   // [5,1024]
    const float* pemb  = (const float*)d_in[5];   // [128,1024]
    const float* w1    = (const float*)d_in[6];   // [5,256]
    const float* b1    = (const float*)d_in[7];   // [256]
    const float* w2    = (const float*)d_in[8];   // [256,1024]
    const float* b2    = (const float*)d_in[9];   // [1024]
    const float* tw    = (const float*)d_in[10];  // [768,1024]
    const float* tb    = (const float*)d_in[11];  // [1024]
    const float* femb  = (const float*)d_in[12];  // [128,1024]
    float*       out   = (float*)d_out;

    const long long emb_elems = (long long)BB * SS * DD;
    const int write_mask = (out_size >= emb_elems + BB * SS) ? 1 : 0;

    // Kernel 1: hidden + A-pack + mask
    const int total1 = BB * KTOT + BB * SS;
    prep_kernel<<<(total1 + 255) / 256, 256>>>(
        types, style, cap, w1, b1, out + emb_elems, write_mask);

    // Kernel 2: combined = A @ [W2;Tw] + bias
    gemm_kernel<<<dim3(DD / 64, BB / 32), 256>>>(w2, tw, b2, tb);

    // Kernel 3: embedding assembly
    emb_kernel<<<dim3(BB / 8, DD / 128), 128>>>(types, inds, temb, pemb, femb, out);
}

// round 5
// speedup vs baseline: 2.6389x; 2.6389x over previous
#include <cuda_runtime.h>

// Problem constants (fixed shapes)
#define BB    256      // batch
#define SS    128      // sequence
#define DD    1024     // d_model
#define DQ    256      // style hidden
#define TXT   768      // caption dim
#define KTOT  1024     // DQ + TXT (concat GEMM K)
#define NSPLIT 4
#define KSPL  256      // KTOT / NSPLIT  (aligned with DQ boundary!)

// Device scratch (no allocation allowed)
__device__ float g_A[BB * KTOT];              // [hidden(256) | captions(768)]
__device__ float g_part[NSPLIT * BB * DD];    // split-K partials
__device__ float g_comb[BB * DD];             // final combined embed

// ---- packed f32x2 helpers (FFMA2 path, sm_103a) -------------------------
__device__ __forceinline__ unsigned long long pk2(float lo, float hi) {
    unsigned long long r;
    asm("mov.b64 %0, {%1, %2};" : "=l"(r) : "f"(lo), "f"(hi));
    return r;
}
__device__ __forceinline__ void fma2(unsigned long long& d,
                                     unsigned long long a, unsigned long long b) {
    asm("fma.rn.f32x2 %0, %1, %2, %0;" : "+l"(d) : "l"(a), "l"(b));
}
__device__ __forceinline__ float2 up2(unsigned long long v) {
    float2 f;
    asm("mov.b64 {%0, %1}, %2;" : "=f"(f.x), "=f"(f.y) : "l"(v));
    return f;
}

// ---------------------------------------------------------------------------
// Kernel 1 (vectorized): A-pack = [relu(style@W1+b1) | captions], plus the
// padding mask (types==0) as 0/1 floats appended after emb in d_out.
// All float4. 65536 A-float4s + 8192 mask-float4s.
// ---------------------------------------------------------------------------
__global__ void __launch_bounds__(256) prep_kernel(
    const int*   __restrict__ types,
    const float* __restrict__ style,   // [B,5]
    const float* __restrict__ cap,     // [B,768]
    const float* __restrict__ w1,      // [5,256]
    const float* __restrict__ b1,      // [256]
    float*       __restrict__ out_mask,
    int          write_mask)
{
    int i4 = blockIdx.x * 256 + threadIdx.x;
    if (i4 < BB * KTOT / 4) {
        int b  = i4 >> 8;
        int k4 = (i4 & 255) << 2;
        float4 v;
        if (k4 < DQ) {
            const float* srow = style + b * 5;
            float s0 = srow[0], s1 = srow[1], s2 = srow[2], s3 = srow[3], s4 = srow[4];
            float4 acc = *reinterpret_cast<const float4*>(b1 + k4);
            #define STEP(si, row) { \
                float4 w = *reinterpret_cast<const float4*>(w1 + (row)*DQ + k4); \
                acc.x = fmaf(si, w.x, acc.x); acc.y = fmaf(si, w.y, acc.y); \
                acc.z = fmaf(si, w.z, acc.z); acc.w = fmaf(si, w.w, acc.w); }
            STEP(s0, 0) STEP(s1, 1) STEP(s2, 2) STEP(s3, 3) STEP(s4, 4)
            #undef STEP
            v.x = fmaxf(acc.x, 0.0f); v.y = fmaxf(acc.y, 0.0f);
            v.z = fmaxf(acc.z, 0.0f); v.w = fmaxf(acc.w, 0.0f);
        } else {
            v = *reinterpret_cast<const float4*>(cap + b * TXT + (k4 - DQ));
        }
        *reinterpret_cast<float4*>(&g_A[b * KTOT + k4]) = v;
    } else if (write_mask) {
        int m4 = i4 - BB * KTOT / 4;
        if (m4 < BB * SS / 4) {
            int4 t = *reinterpret_cast<const int4*>(types + m4 * 4);
            float4 mv = make_float4(t.x == 0 ? 1.0f : 0.0f, t.y == 0 ? 1.0f : 0.0f,
                                    t.z == 0 ? 1.0f : 0.0f, t.w == 0 ? 1.0f : 0.0f);
            *reinterpret_cast<float4*>(out_mask + m4 * 4) = mv;
        }
    }
}

// ---------------------------------------------------------------------------
// Kernel 2: split-K SGEMM with packed FFMA2.
// g_part[sp] += A[32,Kspl] @ W[Kspl,128] per block.
// BM=32, BN=128, BK=32, 256 threads, 2m x 8n micro-tile (8 f32x2 accs).
// Grid (8 n, 8 m, 4 split) = 256 blocks. Split s==0 reads w2, s>=1 reads tw.
// ---------------------------------------------------------------------------
__global__ void __launch_bounds__(256) gemm_kernel(
    const float* __restrict__ w2,   // [256,1024]
    const float* __restrict__ tw)   // [768,1024]
{
    __shared__ float  As[32][34];    // [k][m], padded: row start 8B-aligned
    __shared__ float4 Bs[32][32];    // [k][n/4]

    const int tid = threadIdx.x;
    const int n0  = blockIdx.x * 128;
    const int m0  = blockIdx.y * 32;
    const int sp  = blockIdx.z;
    const int ks  = sp * KSPL;
    // split-aligned weight base: sp==0 -> w2 rows 0..255; sp>=1 -> tw rows ks-256..
    const float* W = (sp == 0) ? w2 : (tw + (ks - DQ) * DD);

    const int tx = tid & 15;         // 16 n-groups
    const int ty = tid >> 4;         // 16 m-groups of 2 rows

    unsigned long long acc[2][2][2] = {};  // [m][half][pair]  (pair = 2 n)

    for (int k0 = 0; k0 < KSPL; k0 += 32) {
        // A tile 32m x 32k: 1 float4 per thread, transpose into As[k][m]
        {
            int m  = tid >> 3;
            int kq = (tid & 7) * 4;
            float4 v = *reinterpret_cast<const float4*>(
                &g_A[(m0 + m) * KTOT + ks + k0 + kq]);
            As[kq + 0][m] = v.x; As[kq + 1][m] = v.y;
            As[kq + 2][m] = v.z; As[kq + 3][m] = v.w;
        }
        // B tile 32k x 128n: 4 float4 per thread, fully coalesced
        #pragma unroll
        for (int i = 0; i < 4; i++) {
            int idx = tid + i * 256;
            int r   = idx >> 5;
            int c4  = idx & 31;
            Bs[r][c4] = *reinterpret_cast<const float4*>(
                W + (k0 + r) * DD + n0 + c4 * 4);
        }
        __syncthreads();

        #pragma unroll
        for (int k = 0; k < 32; k++) {
            float2 a = *reinterpret_cast<const float2*>(&As[k][2 * ty]);
            unsigned long long a0 = pk2(a.x, a.x);
            unsigned long long a1 = pk2(a.y, a.y);
            // two contiguous float4 reads per lane -> conflict-free LDS.128
            ulonglong2 bL = *reinterpret_cast<const ulonglong2*>(&Bs[k][tx]);
            ulonglong2 bH = *reinterpret_cast<const ulonglong2*>(&Bs[k][16 + tx]);
            fma2(acc[0][0][0], a0, bL.x); fma2(acc[0][0][1], a0, bL.y);
            fma2(acc[0][1][0], a0, bH.x); fma2(acc[0][1][1], a0, bH.y);
            fma2(acc[1][0][0], a1, bL.x); fma2(acc[1][0][1], a1, bL.y);
            fma2(acc[1][1][0], a1, bH.x); fma2(acc[1][1][1], a1, bH.y);
        }
        __syncthreads();
    }

    // Epilogue: store partials (each split owns its slice; no init needed)
    float* base = g_part + sp * (BB * DD);
    #pragma unroll
    for (int r = 0; r < 2; r++) {
        int m = m0 + 2 * ty + r;
        #pragma unroll
        for (int h = 0; h < 2; h++) {
            float2 p0 = up2(acc[r][h][0]);
            float2 p1 = up2(acc[r][h][1]);
            float4 o = make_float4(p0.x, p0.y, p1.x, p1.y);
            *reinterpret_cast<float4*>(
                &base[m * DD + n0 + 64 * h + 4 * tx]) = o;
        }
    }
}

// ---------------------------------------------------------------------------
// Kernel 3: g_comb = sum of 4 split partials + (b2 + tb). 65536 float4s.
// ---------------------------------------------------------------------------
__global__ void __launch_bounds__(256) reduce_kernel(
    const float* __restrict__ b2, const float* __restrict__ tb)
{
    int i4 = blockIdx.x * 256 + threadIdx.x;      // 0..65535
    int n  = (i4 & 255) * 4;                       // column within DD
    const float4* p = reinterpret_cast<const float4*>(g_part);
    const int stride = BB * DD / 4;
    float4 s0 = p[i4], s1 = p[i4 + stride], s2 = p[i4 + 2 * stride], s3 = p[i4 + 3 * stride];
    float4 v2 = *reinterpret_cast<const float4*>(b2 + n);
    float4 vt = *reinterpret_cast<const float4*>(tb + n);
    float4 o;
    o.x = s0.x + s1.x + s2.x + s3.x + v2.x + vt.x;
    o.y = s0.y + s1.y + s2.y + s3.y + v2.y + vt.y;
    o.z = s0.z + s1.z + s2.z + s3.z + v2.z + vt.z;
    o.w = s0.w + s1.w + s2.w + s3.w + v2.w + vt.w;
    reinterpret_cast<float4*>(g_comb)[i4] = o;
}

// ---------------------------------------------------------------------------
// Kernel 4: out[b,s,d] = temb[t] + pemb[ix] + femb[s] + (t==1)*comb[b]
// 256 threads: thread = (s-group sg 0..15, d4 0..15). d-slab = 64 floats.
// femb[s][d4] is invariant across the 16-batch loop -> held in registers.
// pemb slab (32KB) + temb stay L1-resident. All float4.
// Grid (16 batch-chunks, 16 slabs) = 256 blocks.
// ---------------------------------------------------------------------------
__global__ void __launch_bounds__(256) emb_kernel(
    const int*   __restrict__ types,
    const int*   __restrict__ inds,
    const float* __restrict__ temb,   // [5,1024]
    const float* __restrict__ pemb,   // [128,1024]
    const float* __restrict__ femb,   // [128,1024]
    float*       __restrict__ out)
{
    const int d4 = threadIdx.x & 15;
    const int sg = threadIdx.x >> 4;
    const int d  = blockIdx.y * 64 + d4 * 4;
    const int b0 = blockIdx.x * 16;

    // final_pos_emb for this thread's 8 s-values, loop-invariant
    float4 fr[8];
    #pragma unroll
    for (int j = 0; j < 8; j++)
        fr[j] = *reinterpret_cast<const float4*>(&femb[(sg + j * 16) * DD + d]);

    for (int bb = 0; bb < 16; bb++) {
        const int b = b0 + bb;
        const float4 comb = *reinterpret_cast<const float4*>(&g_comb[b * DD + d]);
        const int* tr = types + b * SS;
        const int* ir = inds + b * SS;
        float* ob = out + (size_t)b * SS * DD + d;

        #pragma unroll
        for (int j = 0; j < 8; j++) {
            const int s   = sg + j * 16;
            const int t   = __ldg(tr + s);
            const int ixv = __ldg(ir + s);
            float4 te = *reinterpret_cast<const float4*>(&temb[t * DD + d]);
            float4 pe = *reinterpret_cast<const float4*>(&pemb[ixv * DD + d]);
            float4 v;
            v.x = fr[j].x + te.x + pe.x;
            v.y = fr[j].y + te.y + pe.y;
            v.z = fr[j].z + te.z + pe.z;
            v.w = fr[j].w + te.w + pe.w;
            if (t == 1) {
                v.x += comb.x; v.y += comb.y; v.z += comb.z; v.w += comb.w;
            }
            *reinterpret_cast<float4*>(ob + (size_t)s * DD) = v;
        }
    }
}

// ---------------------------------------------------------------------------
extern "C" void kernel_launch(void* const* d_in, const int* in_sizes, int n_in,
                              void* d_out, int out_size)
{
    const int*   types = (const int*)  d_in[0];   // [256,128] i32
    const int*   inds  = (const int*)  d_in[1];   // [256,128] i32
    const float* style = (const float*)d_in[2];   // [256,5]
    const float* cap   = (const float*)d_in[3];   // [256,768]
    const float* temb  = (const float*)d_in[4];   // [5,1024]
    const float* pemb  = (const float*)d_in[5];   // [128,1024]
    const float* w1    = (const float*)d_in[6];   // [5,256]
    const float* b1    = (const float*)d_in[7];   // [256]
    const float* w2    = (const float*)d_in[8];   // [256,1024]
    const float* b2    = (const float*)d_in[9];   // [1024]
    const float* tw    = (const float*)d_in[10];  // [768,1024]
    const float* tb    = (const float*)d_in[11];  // [1024]
    const float* femb  = (const float*)d_in[12];  // [128,1024]
    float*       out   = (float*)d_out;

    const long long emb_elems = (long long)BB * SS * DD;
    const int write_mask = (out_size >= emb_elems + BB * SS) ? 1 : 0;

    // 1: A-pack + mask (73728 float4 slots -> 288 blocks)
    prep_kernel<<<288, 256>>>(types, style, cap, w1, b1, out + emb_elems, write_mask);

    // 2: split-K FFMA2 SGEMM -> g_part
    gemm_kernel<<<dim3(DD / 128, BB / 32, NSPLIT), 256>>>(w2, tw);

    // 3: partials + bias -> g_comb
    reduce_kernel<<<BB * DD / 4 / 256, 256>>>(b2, tb);

    // 4: embedding assembly
    emb_kernel<<<dim3(BB / 16, DD / 64), 256>>>(types, inds, temb, pemb, femb, out);
}

// round 6
// speedup vs baseline: 3.4879x; 1.3218x over previous
#include <cuda_runtime.h>

// Problem constants (fixed shapes)
#define BB    256      // batch
#define SS    128      // sequence
#define DD    1024     // d_model
#define DQ    256      // style hidden
#define TXT   768      // caption dim
#define KTOT  1024     // DQ + TXT (concat GEMM K)
#define NSPLIT 8
#define KSPL  128      // KTOT / NSPLIT (splits 0,1 -> w2; 2..7 -> tw)

// Device scratch (no allocation allowed)
__device__ float g_A[BB * KTOT];              // [hidden(256) | captions(768)]
__device__ float g_part[NSPLIT * BB * DD];    // split-K partials (8 MB)

// ---- packed f32x2 helpers (FFMA2 path, sm_103a) -------------------------
__device__ __forceinline__ unsigned long long pk2(float lo, float hi) {
    unsigned long long r;
    asm("mov.b64 %0, {%1, %2};" : "=l"(r) : "f"(lo), "f"(hi));
    return r;
}
__device__ __forceinline__ void fma2(unsigned long long& d,
                                     unsigned long long a, unsigned long long b) {
    asm("fma.rn.f32x2 %0, %1, %2, %0;" : "+l"(d) : "l"(a), "l"(b));
}
__device__ __forceinline__ float2 up2(unsigned long long v) {
    float2 f;
    asm("mov.b64 {%0, %1}, %2;" : "=f"(f.x), "=f"(f.y) : "l"(v));
    return f;
}

// ---------------------------------------------------------------------------
// Kernel 1: A-pack = [relu(style@W1+b1) | captions], plus padding mask
// (types==0) as 0/1 floats appended after emb in d_out. All float4.
// ---------------------------------------------------------------------------
__global__ void __launch_bounds__(256) prep_kernel(
    const int*   __restrict__ types,
    const float* __restrict__ style,   // [B,5]
    const float* __restrict__ cap,     // [B,768]
    const float* __restrict__ w1,      // [5,256]
    const float* __restrict__ b1,      // [256]
    float*       __restrict__ out_mask,
    int          write_mask)
{
    int i4 = blockIdx.x * 256 + threadIdx.x;
    if (i4 < BB * KTOT / 4) {
        int b  = i4 >> 8;
        int k4 = (i4 & 255) << 2;
        float4 v;
        if (k4 < DQ) {
            const float* srow = style + b * 5;
            float s0 = srow[0], s1 = srow[1], s2 = srow[2], s3 = srow[3], s4 = srow[4];
            float4 acc = *reinterpret_cast<const float4*>(b1 + k4);
            #define STEP(si, row) { \
                float4 w = *reinterpret_cast<const float4*>(w1 + (row)*DQ + k4); \
                acc.x = fmaf(si, w.x, acc.x); acc.y = fmaf(si, w.y, acc.y); \
                acc.z = fmaf(si, w.z, acc.z); acc.w = fmaf(si, w.w, acc.w); }
            STEP(s0, 0) STEP(s1, 1) STEP(s2, 2) STEP(s3, 3) STEP(s4, 4)
            #undef STEP
            v.x = fmaxf(acc.x, 0.0f); v.y = fmaxf(acc.y, 0.0f);
            v.z = fmaxf(acc.z, 0.0f); v.w = fmaxf(acc.w, 0.0f);
        } else {
            v = *reinterpret_cast<const float4*>(cap + b * TXT + (k4 - DQ));
        }
        *reinterpret_cast<float4*>(&g_A[b * KTOT + k4]) = v;
    } else if (write_mask) {
        int m4 = i4 - BB * KTOT / 4;
        if (m4 < BB * SS / 4) {
            int4 t = *reinterpret_cast<const int4*>(types + m4 * 4);
            float4 mv = make_float4(t.x == 0 ? 1.0f : 0.0f, t.y == 0 ? 1.0f : 0.0f,
                                    t.z == 0 ? 1.0f : 0.0f, t.w == 0 ? 1.0f : 0.0f);
            *reinterpret_cast<float4*>(out_mask + m4 * 4) = mv;
        }
    }
}

// ---------------------------------------------------------------------------
// Kernel 2: split-K SGEMM with packed FFMA2 (NSPLIT=8, K=128 per split).
// BM=32, BN=128, BK=32, 256 threads, 2m x 8n micro-tile (8 f32x2 accs).
// Grid (8 n, 8 m, 8 split) = 512 blocks (~3.5 CTAs/SM).
// ---------------------------------------------------------------------------
__global__ void __launch_bounds__(256) gemm_kernel(
    const float* __restrict__ w2,   // [256,1024]
    const float* __restrict__ tw)   // [768,1024]
{
    __shared__ float  As[32][34];
    __shared__ float4 Bs[32][32];

    const int tid = threadIdx.x;
    const int n0  = blockIdx.x * 128;
    const int m0  = blockIdx.y * 32;
    const int sp  = blockIdx.z;
    const int ks  = sp * KSPL;
    const float* W = (sp < 2) ? (w2 + ks * DD) : (tw + (ks - DQ) * DD);

    const int tx = tid & 15;
    const int ty = tid >> 4;

    unsigned long long acc[2][2][2] = {};

    for (int k0 = 0; k0 < KSPL; k0 += 32) {
        {
            int m  = tid >> 3;
            int kq = (tid & 7) * 4;
            float4 v = *reinterpret_cast<const float4*>(
                &g_A[(m0 + m) * KTOT + ks + k0 + kq]);
            As[kq + 0][m] = v.x; As[kq + 1][m] = v.y;
            As[kq + 2][m] = v.z; As[kq + 3][m] = v.w;
        }
        #pragma unroll
        for (int i = 0; i < 4; i++) {
            int idx = tid + i * 256;
            int r   = idx >> 5;
            int c4  = idx & 31;
            Bs[r][c4] = *reinterpret_cast<const float4*>(
                W + (k0 + r) * DD + n0 + c4 * 4);
        }
        __syncthreads();

        #pragma unroll
        for (int k = 0; k < 32; k++) {
            float2 a = *reinterpret_cast<const float2*>(&As[k][2 * ty]);
            unsigned long long a0 = pk2(a.x, a.x);
            unsigned long long a1 = pk2(a.y, a.y);
            ulonglong2 bL = *reinterpret_cast<const ulonglong2*>(&Bs[k][tx]);
            ulonglong2 bH = *reinterpret_cast<const ulonglong2*>(&Bs[k][16 + tx]);
            fma2(acc[0][0][0], a0, bL.x); fma2(acc[0][0][1], a0, bL.y);
            fma2(acc[0][1][0], a0, bH.x); fma2(acc[0][1][1], a0, bH.y);
            fma2(acc[1][0][0], a1, bL.x); fma2(acc[1][0][1], a1, bL.y);
            fma2(acc[1][1][0], a1, bH.x); fma2(acc[1][1][1], a1, bH.y);
        }
        __syncthreads();
    }

    float* base = g_part + sp * (BB * DD);
    #pragma unroll
    for (int r = 0; r < 2; r++) {
        int m = m0 + 2 * ty + r;
        #pragma unroll
        for (int h = 0; h < 2; h++) {
            float2 p0 = up2(acc[r][h][0]);
            float2 p1 = up2(acc[r][h][1]);
            float4 o = make_float4(p0.x, p0.y, p1.x, p1.y);
            *reinterpret_cast<float4*>(&base[m * DD + n0 + 64 * h + 4 * tx]) = o;
        }
    }
}

// ---------------------------------------------------------------------------
// Kernel 3 (fused reduce + assembly):
//   comb[d] = sum_sp g_part[sp][b][d] + b2[d] + tb[d]   (computed once/block)
//   out[b,s,d] = temb[t] + pemb[ix] + femb[s] + (t==1)*comb
// Grid (BB=256, DD/128=8) = 2048 blocks, 512 threads.
// warp = one s-position row segment (32 lanes x float4 = 512B, fully coalesced)
// Each warp handles 8 consecutive s positions, fully unrolled for MLP.
// ---------------------------------------------------------------------------
__global__ void __launch_bounds__(512, 2) emb_kernel(
    const int*   __restrict__ types,
    const int*   __restrict__ inds,
    const float* __restrict__ temb,   // [5,1024]
    const float* __restrict__ pemb,   // [128,1024]
    const float* __restrict__ femb,   // [128,1024]
    const float* __restrict__ b2,     // [1024]
    const float* __restrict__ tb,     // [1024]
    float*       __restrict__ out)
{
    __shared__ float4 combS[32];
    __shared__ int    ts[SS];
    __shared__ int    ix[SS];

    const int tid = threadIdx.x;
    const int b   = blockIdx.x;
    const int d0  = blockIdx.y * 128;
    const int d4  = tid & 31;          // 32 float4 lanes = 128 floats
    const int sg  = tid >> 5;          // warp id = s-group (0..15)
    const int d   = d0 + d4 * 4;

    if (tid < SS) {
        ts[tid] = types[b * SS + tid];
        ix[tid] = inds[b * SS + tid];
    }
    if (tid < 32) {
        // fused split-K reduce + bias for this block's 128-d slab
        float4 acc = *reinterpret_cast<const float4*>(b2 + d);
        float4 vt  = *reinterpret_cast<const float4*>(tb + d);
        acc.x += vt.x; acc.y += vt.y; acc.z += vt.z; acc.w += vt.w;
        #pragma unroll
        for (int sp = 0; sp < NSPLIT; sp++) {
            float4 p = *reinterpret_cast<const float4*>(
                &g_part[sp * (BB * DD) + b * DD + d]);
            acc.x += p.x; acc.y += p.y; acc.z += p.z; acc.w += p.w;
        }
        combS[tid] = acc;
    }
    __syncthreads();

    const float4 comb = combS[d4];
    float* ob = out + (size_t)b * SS * DD + d;

    #pragma unroll
    for (int j = 0; j < 8; j++) {
        const int s   = sg * 8 + j;
        const int t   = ts[s];
        const int iv  = ix[s];
        float4 te = *reinterpret_cast<const float4*>(&temb[t * DD + d]);
        float4 pe = *reinterpret_cast<const float4*>(&pemb[iv * DD + d]);
        float4 fe = *reinterpret_cast<const float4*>(&femb[s * DD + d]);
        float4 v;
        v.x = te.x + pe.x + fe.x;
        v.y = te.y + pe.y + fe.y;
        v.z = te.z + pe.z + fe.z;
        v.w = te.w + pe.w + fe.w;
        if (t == 1) {
            v.x += comb.x; v.y += comb.y; v.z += comb.z; v.w += comb.w;
        }
        *reinterpret_cast<float4*>(ob + (size_t)s * DD) = v;
    }
}

// ---------------------------------------------------------------------------
extern "C" void kernel_launch(void* const* d_in, const int* in_sizes, int n_in,
                              void* d_out, int out_size)
{
    const int*   types = (const int*)  d_in[0];   // [256,128] i32
    const int*   inds  = (const int*)  d_in[1];   // [256,128] i32
    const float* style = (const float*)d_in[2];   // [256,5]
    const float* cap   = (const float*)d_in[3];   // [256,768]
    const float* temb  = (const float*)d_in[4];   // [5,1024]
    const float* pemb  = (const float*)d_in[5];   // [128,1024]
    const float* w1    = (const float*)d_in[6];   // [5,256]
    const float* b1    = (const float*)d_in[7];   // [256]
    const float* w2    = (const float*)d_in[8];   // [256,1024]
    const float* b2    = (const float*)d_in[9];   // [1024]
    const float* tw    = (const float*)d_in[10];  // [768,1024]
    const float* tb    = (const float*)d_in[11];  // [1024]
    const float* femb  = (const float*)d_in[12];  // [128,1024]
    float*       out   = (float*)d_out;

    const long long emb_elems = (long long)BB * SS * DD;
    const int write_mask = (out_size >= emb_elems + BB * SS) ? 1 : 0;

    // 1: A-pack + mask
    prep_kernel<<<288, 256>>>(types, style, cap, w1, b1, out + emb_elems, write_mask);

    // 2: split-K FFMA2 SGEMM -> g_part (8 splits)
    gemm_kernel<<<dim3(DD / 128, BB / 32, NSPLIT), 256>>>(w2, tw);

    // 3: fused reduce+bias+embedding assembly
    emb_kernel<<<dim3(BB, DD / 128), 512>>>(
        types, inds, temb, pemb, femb, b2, tb, out);
}

// round 7
// speedup vs baseline: 3.8634x; 1.1076x over previous
#include <cuda_runtime.h>

// Problem constants (fixed shapes)
#define BB    256      // batch
#define SS    128      // sequence
#define DD    1024     // d_model
#define DQ    256      // style hidden
#define TXT   768      // caption dim
#define KTOT  1024     // DQ + TXT (concat GEMM K)
#define NSPLIT 8
#define KSPL  128      // KTOT / NSPLIT (splits 0,1 -> hidden; 2..7 -> captions)

// Device scratch (no allocation allowed)
__device__ float g_h[BB * DQ];                // relu(style@W1+b1)  (256 KB)
__device__ float g_part[NSPLIT * BB * DD];    // split-K partials (8 MB)
__device__ float g_comb[BB * DD];             // combined embed (1 MB)

// ---- packed f32x2 helpers (FFMA2 path, sm_103a) -------------------------
__device__ __forceinline__ unsigned long long pk2(float lo, float hi) {
    unsigned long long r;
    asm("mov.b64 %0, {%1, %2};" : "=l"(r) : "f"(lo), "f"(hi));
    return r;
}
__device__ __forceinline__ void fma2(unsigned long long& d,
                                     unsigned long long a, unsigned long long b) {
    asm("fma.rn.f32x2 %0, %1, %2, %0;" : "+l"(d) : "l"(a), "l"(b));
}
__device__ __forceinline__ float2 up2(unsigned long long v) {
    float2 f;
    asm("mov.b64 {%0, %1}, %2;" : "=f"(f.x), "=f"(f.y) : "l"(v));
    return f;
}

// ---------------------------------------------------------------------------
// Kernel 1: hidden = relu(style@W1+b1)  (GEMM reads captions directly now)
// plus padding mask (types==0) appended after emb in d_out. All float4.
// 16384 hidden-float4s + 8192 mask-float4s = 96 blocks x 256.
// ---------------------------------------------------------------------------
__global__ void __launch_bounds__(256) prep_kernel(
    const int*   __restrict__ types,
    const float* __restrict__ style,   // [B,5]
    const float* __restrict__ w1,      // [5,256]
    const float* __restrict__ b1,      // [256]
    float*       __restrict__ out_mask,
    int          write_mask)
{
    int i4 = blockIdx.x * 256 + threadIdx.x;
    if (i4 < BB * DQ / 4) {
        int b  = i4 >> 6;
        int k4 = (i4 & 63) << 2;
        const float* srow = style + b * 5;
        float s0 = srow[0], s1 = srow[1], s2 = srow[2], s3 = srow[3], s4 = srow[4];
        float4 acc = *reinterpret_cast<const float4*>(b1 + k4);
        #define STEP(si, row) { \
            float4 w = *reinterpret_cast<const float4*>(w1 + (row)*DQ + k4); \
            acc.x = fmaf(si, w.x, acc.x); acc.y = fmaf(si, w.y, acc.y); \
            acc.z = fmaf(si, w.z, acc.z); acc.w = fmaf(si, w.w, acc.w); }
        STEP(s0, 0) STEP(s1, 1) STEP(s2, 2) STEP(s3, 3) STEP(s4, 4)
        #undef STEP
        float4 v = make_float4(fmaxf(acc.x, 0.0f), fmaxf(acc.y, 0.0f),
                               fmaxf(acc.z, 0.0f), fmaxf(acc.w, 0.0f));
        *reinterpret_cast<float4*>(&g_h[b * DQ + k4]) = v;
    } else if (write_mask) {
        int m4 = i4 - BB * DQ / 4;
        if (m4 < BB * SS / 4) {
            int4 t = *reinterpret_cast<const int4*>(types + m4 * 4);
            float4 mv = make_float4(t.x == 0 ? 1.0f : 0.0f, t.y == 0 ? 1.0f : 0.0f,
                                    t.z == 0 ? 1.0f : 0.0f, t.w == 0 ? 1.0f : 0.0f);
            *reinterpret_cast<float4*>(out_mask + m4 * 4) = mv;
        }
    }
}

// ---------------------------------------------------------------------------
// Kernel 2: split-K SGEMM with packed FFMA2 (NSPLIT=8, K=128 per split).
// A rows come from g_h (splits 0,1) or directly from captions (splits 2..7).
// BM=32, BN=128, BK=32, 256 threads, 2m x 8n micro-tile.
// Grid (8 n, 8 m, 8 split) = 512 blocks.
// ---------------------------------------------------------------------------
__global__ void __launch_bounds__(256) gemm_kernel(
    const float* __restrict__ cap,  // [256,768]
    const float* __restrict__ w2,   // [256,1024]
    const float* __restrict__ tw)   // [768,1024]
{
    __shared__ float  As[32][34];
    __shared__ float4 Bs[32][32];

    const int tid = threadIdx.x;
    const int n0  = blockIdx.x * 128;
    const int m0  = blockIdx.y * 32;
    const int sp  = blockIdx.z;
    const int ks  = sp * KSPL;
    const float* W     = (sp < 2) ? (w2 + ks * DD) : (tw + (ks - DQ) * DD);
    const float* Abase = (sp < 2) ? (g_h + ks)     : (cap + (ks - DQ));
    const int    Astr  = (sp < 2) ? DQ : TXT;

    const int tx = tid & 15;
    const int ty = tid >> 4;

    unsigned long long acc[2][2][2] = {};

    for (int k0 = 0; k0 < KSPL; k0 += 32) {
        {
            int m  = tid >> 3;
            int kq = (tid & 7) * 4;
            float4 v = *reinterpret_cast<const float4*>(
                Abase + (m0 + m) * Astr + k0 + kq);
            As[kq + 0][m] = v.x; As[kq + 1][m] = v.y;
            As[kq + 2][m] = v.z; As[kq + 3][m] = v.w;
        }
        #pragma unroll
        for (int i = 0; i < 4; i++) {
            int idx = tid + i * 256;
            int r   = idx >> 5;
            int c4  = idx & 31;
            Bs[r][c4] = *reinterpret_cast<const float4*>(
                W + (k0 + r) * DD + n0 + c4 * 4);
        }
        __syncthreads();

        #pragma unroll
        for (int k = 0; k < 32; k++) {
            float2 a = *reinterpret_cast<const float2*>(&As[k][2 * ty]);
            unsigned long long a0 = pk2(a.x, a.x);
            unsigned long long a1 = pk2(a.y, a.y);
            ulonglong2 bL = *reinterpret_cast<const ulonglong2*>(&Bs[k][tx]);
            ulonglong2 bH = *reinterpret_cast<const ulonglong2*>(&Bs[k][16 + tx]);
            fma2(acc[0][0][0], a0, bL.x); fma2(acc[0][0][1], a0, bL.y);
            fma2(acc[0][1][0], a0, bH.x); fma2(acc[0][1][1], a0, bH.y);
            fma2(acc[1][0][0], a1, bL.x); fma2(acc[1][0][1], a1, bL.y);
            fma2(acc[1][1][0], a1, bH.x); fma2(acc[1][1][1], a1, bH.y);
        }
        __syncthreads();
    }

    float* base = g_part + sp * (BB * DD);
    #pragma unroll
    for (int r = 0; r < 2; r++) {
        int m = m0 + 2 * ty + r;
        #pragma unroll
        for (int h = 0; h < 2; h++) {
            float2 p0 = up2(acc[r][h][0]);
            float2 p1 = up2(acc[r][h][1]);
            float4 o = make_float4(p0.x, p0.y, p1.x, p1.y);
            *reinterpret_cast<float4*>(&base[m * DD + n0 + 64 * h + 4 * tx]) = o;
        }
    }
}

// ---------------------------------------------------------------------------
// Kernel 3: g_comb = sum of 8 split partials + (b2 + tb). 65536 float4s.
// ---------------------------------------------------------------------------
__global__ void __launch_bounds__(256) reduce_kernel(
    const float* __restrict__ b2, const float* __restrict__ tb)
{
    int i4 = blockIdx.x * 256 + threadIdx.x;      // 0..65535
    int n  = (i4 & 255) * 4;
    const float4* p = reinterpret_cast<const float4*>(g_part);
    const int stride = BB * DD / 4;
    float4 v2 = *reinterpret_cast<const float4*>(b2 + n);
    float4 vt = *reinterpret_cast<const float4*>(tb + n);
    float4 o = make_float4(v2.x + vt.x, v2.y + vt.y, v2.z + vt.z, v2.w + vt.w);
    #pragma unroll
    for (int sp = 0; sp < NSPLIT; sp++) {
        float4 s = p[i4 + sp * stride];
        o.x += s.x; o.y += s.y; o.z += s.z; o.w += s.w;
    }
    reinterpret_cast<float4*>(g_comb)[i4] = o;
}

// ---------------------------------------------------------------------------
// Kernel 4: assembly with SMEM-resident tables (kills L2 read amplification).
// Block = (d-slab 128 floats, s-chunk 16, b-chunk 64). 512 threads.
//   smem: pemb slab 64KB + temb slab 2.5KB + types/inds 8KB = 74.5KB -> 2 CTA/SM
//   warp = one s (femb float4 in register); lanes = 32 float4 across the slab.
// Grid (8 dslab, 8 schunk, 4 bchunk) = 256 blocks = one full wave.
// ---------------------------------------------------------------------------
#define EMB_SMEM_BYTES (128*32*16 + 5*32*16 + 2*64*16*4)  // 65536+2560+8192=76288

__global__ void __launch_bounds__(512, 2) emb_kernel(
    const int*   __restrict__ types,
    const int*   __restrict__ inds,
    const float* __restrict__ temb,   // [5,1024]
    const float* __restrict__ pemb,   // [128,1024]
    const float* __restrict__ femb,   // [128,1024]
    float*       __restrict__ out)
{
    extern __shared__ char smem[];
    float4* pembS = reinterpret_cast<float4*>(smem);              // [128][32]
    float4* tembS = pembS + 128 * 32;                             // [5][32]
    int*    tsS   = reinterpret_cast<int*>(tembS + 5 * 32);       // [64][16]
    int*    ixS   = tsS + 64 * 16;                                // [64][16]

    const int tid   = threadIdx.x;
    const int d4    = tid & 31;
    const int sg    = tid >> 5;                 // warp id = local s (0..15)
    const int dsl   = blockIdx.x;               // d-slab (0..7)
    const int s0    = blockIdx.y * 16;
    const int b0    = blockIdx.z * 64;
    const int d     = dsl * 128 + d4 * 4;
    const int s     = s0 + sg;

    // Load pemb/temb slabs (coalesced float4)
    const float4* pemb4 = reinterpret_cast<const float4*>(pemb);
    const float4* temb4 = reinterpret_cast<const float4*>(temb);
    #pragma unroll
    for (int i = tid; i < 128 * 32; i += 512) {
        int row = i >> 5, c = i & 31;
        pembS[i] = pemb4[row * 256 + dsl * 32 + c];
    }
    if (tid < 5 * 32) {
        int row = tid >> 5, c = tid & 31;
        tembS[tid] = temb4[row * 256 + dsl * 32 + c];
    }
    // Load types/inds for (64 b x 16 s) via int4
    {
        int i = tid;                  // 0..511; need 256 int4 per table
        int bb = i >> 1, g = (i & 1) * 4;   // covers 512*... wait 64*16/4 = 256
        if (i < 256) {
            int b_ = i >> 2, q = (i & 3) * 4;
            *reinterpret_cast<int4*>(&tsS[b_ * 16 + q]) =
                *reinterpret_cast<const int4*>(&types[(b0 + b_) * SS + s0 + q]);
        } else if (i < 512) {
            int j = i - 256;
            int b_ = j >> 2, q = (j & 3) * 4;
            *reinterpret_cast<int4*>(&ixS[b_ * 16 + q]) =
                *reinterpret_cast<const int4*>(&inds[(b0 + b_) * SS + s0 + q]);
        }
        (void)bb; (void)g;
    }
    // femb for this warp's s: loop-invariant register
    float4 fr = *reinterpret_cast<const float4*>(&femb[s * DD + d]);
    __syncthreads();

    float* obase = out + (size_t)s * DD + d;

    #pragma unroll 4
    for (int bb = 0; bb < 64; bb++) {
        const int b  = b0 + bb;
        const int t  = tsS[bb * 16 + sg];
        const int iv = ixS[bb * 16 + sg];
        float4 pe = pembS[iv * 32 + d4];
        float4 te = tembS[t * 32 + d4];
        float4 v;
        v.x = fr.x + te.x + pe.x;
        v.y = fr.y + te.y + pe.y;
        v.z = fr.z + te.z + pe.z;
        v.w = fr.w + te.w + pe.w;
        if (t == 1) {   // warp-uniform branch; comb read only when needed
            float4 c = *reinterpret_cast<const float4*>(&g_comb[b * DD + d]);
            v.x += c.x; v.y += c.y; v.z += c.z; v.w += c.w;
        }
        *reinterpret_cast<float4*>(obase + (size_t)b * SS * DD) = v;
    }
}

// ---------------------------------------------------------------------------
extern "C" void kernel_launch(void* const* d_in, const int* in_sizes, int n_in,
                              void* d_out, int out_size)
{
    const int*   types = (const int*)  d_in[0];   // [256,128] i32
    const int*   inds  = (const int*)  d_in[1];   // [256,128] i32
    const float* style = (const float*)d_in[2];   // [256,5]
    const float* cap   = (const float*)d_in[3];   // [256,768]
    const float* temb  = (const float*)d_in[4];   // [5,1024]
    const float* pemb  = (const float*)d_in[5];   // [128,1024]
    const float* w1    = (const float*)d_in[6];   // [5,256]
    const float* b1    = (const float*)d_in[7];   // [256]
    const float* w2    = (const float*)d_in[8];   // [256,1024]
    const float* b2    = (const float*)d_in[9];   // [1024]
    const float* tw    = (const float*)d_in[10];  // [768,1024]
    const float* tb    = (const float*)d_in[11];  // [1024]
    const float* femb  = (const float*)d_in[12];  // [128,1024]
    float*       out   = (float*)d_out;

    const long long emb_elems = (long long)BB * SS * DD;
    const int write_mask = (out_size >= emb_elems + BB * SS) ? 1 : 0;

    cudaFuncSetAttribute(emb_kernel,
                         cudaFuncAttributeMaxDynamicSharedMemorySize,
                         EMB_SMEM_BYTES);

    // 1: hidden + mask (24576 float4 slots -> 96 blocks)
    prep_kernel<<<96, 256>>>(types, style, w1, b1, out + emb_elems, write_mask);

    // 2: split-K FFMA2 SGEMM -> g_part (8 splits; captions read in-place)
    gemm_kernel<<<dim3(DD / 128, BB / 32, NSPLIT), 256>>>(cap, w2, tw);

    // 3: partials + bias -> g_comb
    reduce_kernel<<<BB * DD / 4 / 256, 256>>>(b2, tb);

    // 4: assembly with smem tables
    emb_kernel<<<dim3(8, 8, 4), 512, EMB_SMEM_BYTES>>>(
        types, inds, temb, pemb, femb, out);
}

// round 8
// speedup vs baseline: 4.3511x; 1.1263x over previous
#include <cuda_runtime.h>

// Problem constants (fixed shapes)
#define BB    256      // batch
#define SS    128      // sequence
#define DD    1024     // d_model
#define DQ    256      // style hidden
#define TXT   768      // caption dim
#define KTOT  1024     // DQ + TXT (concat GEMM K)
#define NSPLIT 8
#define KSPL  128      // KTOT / NSPLIT (splits 0,1 -> hidden; 2..7 -> captions)

// Device scratch (no allocation allowed)
__device__ float g_h[BB * DQ];                // relu(style@W1+b1)
__device__ float g_part[NSPLIT * BB * DD];    // split-K partials (8 MB)
__device__ float g_comb[BB * DD];             // combined embed (1 MB)

// ---- packed f32x2 helpers (FFMA2 path, sm_103a) -------------------------
__device__ __forceinline__ unsigned long long pk2(float lo, float hi) {
    unsigned long long r;
    asm("mov.b64 %0, {%1, %2};" : "=l"(r) : "f"(lo), "f"(hi));
    return r;
}
__device__ __forceinline__ void fma2(unsigned long long& d,
                                     unsigned long long a, unsigned long long b) {
    asm("fma.rn.f32x2 %0, %1, %2, %0;" : "+l"(d) : "l"(a), "l"(b));
}
__device__ __forceinline__ float2 up2(unsigned long long v) {
    float2 f;
    asm("mov.b64 {%0, %1}, %2;" : "=f"(f.x), "=f"(f.y) : "l"(v));
    return f;
}

// ---------------------------------------------------------------------------
// Kernel 1: hidden = relu(style@W1+b1) + padding mask appended after emb.
// ---------------------------------------------------------------------------
__global__ void __launch_bounds__(256) prep_kernel(
    const int*   __restrict__ types,
    const float* __restrict__ style,   // [B,5]
    const float* __restrict__ w1,      // [5,256]
    const float* __restrict__ b1,      // [256]
    float*       __restrict__ out_mask,
    int          write_mask)
{
    int i4 = blockIdx.x * 256 + threadIdx.x;
    if (i4 < BB * DQ / 4) {
        int b  = i4 >> 6;
        int k4 = (i4 & 63) << 2;
        const float* srow = style + b * 5;
        float s0 = srow[0], s1 = srow[1], s2 = srow[2], s3 = srow[3], s4 = srow[4];
        float4 acc = *reinterpret_cast<const float4*>(b1 + k4);
        #define STEP(si, row) { \
            float4 w = *reinterpret_cast<const float4*>(w1 + (row)*DQ + k4); \
            acc.x = fmaf(si, w.x, acc.x); acc.y = fmaf(si, w.y, acc.y); \
            acc.z = fmaf(si, w.z, acc.z); acc.w = fmaf(si, w.w, acc.w); }
        STEP(s0, 0) STEP(s1, 1) STEP(s2, 2) STEP(s3, 3) STEP(s4, 4)
        #undef STEP
        float4 v = make_float4(fmaxf(acc.x, 0.0f), fmaxf(acc.y, 0.0f),
                               fmaxf(acc.z, 0.0f), fmaxf(acc.w, 0.0f));
        *reinterpret_cast<float4*>(&g_h[b * DQ + k4]) = v;
    } else if (write_mask) {
        int m4 = i4 - BB * DQ / 4;
        if (m4 < BB * SS / 4) {
            int4 t = *reinterpret_cast<const int4*>(types + m4 * 4);
            float4 mv = make_float4(t.x == 0 ? 1.0f : 0.0f, t.y == 0 ? 1.0f : 0.0f,
                                    t.z == 0 ? 1.0f : 0.0f, t.w == 0 ? 1.0f : 0.0f);
            *reinterpret_cast<float4*>(out_mask + m4 * 4) = mv;
        }
    }
}

// ---------------------------------------------------------------------------
// Kernel 2: split-K SGEMM, FFMA2, BM=64 BN=128 BK=32, 4m x 8n micro-tile.
// 16 FFMA2 per 48 LDS-bytes per thread-k (2x the intensity of R6).
// Grid (8 n, 4 m, 8 split) = 256 blocks, 256 threads.
// ---------------------------------------------------------------------------
__global__ void __launch_bounds__(256) gemm_kernel(
    const float* __restrict__ cap,  // [256,768]
    const float* __restrict__ w2,   // [256,1024]
    const float* __restrict__ tw)   // [768,1024]
{
    __shared__ float  As[32][68];    // [k][m], 272B row stride (16B aligned)
    __shared__ float4 Bs[32][32];    // [k][n/4]

    const int tid = threadIdx.x;
    const int n0  = blockIdx.x * 128;
    const int m0  = blockIdx.y * 64;
    const int sp  = blockIdx.z;
    const int ks  = sp * KSPL;
    const float* W     = (sp < 2) ? (w2 + ks * DD) : (tw + (ks - DQ) * DD);
    const float* Abase = (sp < 2) ? (g_h + ks)     : (cap + (ks - DQ));
    const int    Astr  = (sp < 2) ? DQ : TXT;

    const int tx = tid & 15;         // 16 n-groups (8 floats each)
    const int ty = tid >> 4;         // 16 m-groups of 4 rows

    unsigned long long acc[4][2][2] = {};   // [m][half][pair]

    for (int k0 = 0; k0 < KSPL; k0 += 32) {
        // A tile 64m x 32k: 2 float4 per thread, transpose into As[k][m]
        #pragma unroll
        for (int i = 0; i < 2; i++) {
            int idx = tid + i * 256;
            int m   = idx >> 3;
            int kq  = (idx & 7) * 4;
            float4 v = *reinterpret_cast<const float4*>(
                Abase + (m0 + m) * Astr + k0 + kq);
            As[kq + 0][m] = v.x; As[kq + 1][m] = v.y;
            As[kq + 2][m] = v.z; As[kq + 3][m] = v.w;
        }
        // B tile 32k x 128n: 4 float4 per thread, coalesced
        #pragma unroll
        for (int i = 0; i < 4; i++) {
            int idx = tid + i * 256;
            int r   = idx >> 5;
            int c4  = idx & 31;
            Bs[r][c4] = *reinterpret_cast<const float4*>(
                W + (k0 + r) * DD + n0 + c4 * 4);
        }
        __syncthreads();

        #pragma unroll
        for (int k = 0; k < 32; k++) {
            float4 a = *reinterpret_cast<const float4*>(&As[k][4 * ty]);
            ulonglong2 bL = *reinterpret_cast<const ulonglong2*>(&Bs[k][tx]);
            ulonglong2 bH = *reinterpret_cast<const ulonglong2*>(&Bs[k][16 + tx]);
            unsigned long long a0 = pk2(a.x, a.x);
            unsigned long long a1 = pk2(a.y, a.y);
            unsigned long long a2 = pk2(a.z, a.z);
            unsigned long long a3 = pk2(a.w, a.w);
            fma2(acc[0][0][0], a0, bL.x); fma2(acc[0][0][1], a0, bL.y);
            fma2(acc[0][1][0], a0, bH.x); fma2(acc[0][1][1], a0, bH.y);
            fma2(acc[1][0][0], a1, bL.x); fma2(acc[1][0][1], a1, bL.y);
            fma2(acc[1][1][0], a1, bH.x); fma2(acc[1][1][1], a1, bH.y);
            fma2(acc[2][0][0], a2, bL.x); fma2(acc[2][0][1], a2, bL.y);
            fma2(acc[2][1][0], a2, bH.x); fma2(acc[2][1][1], a2, bH.y);
            fma2(acc[3][0][0], a3, bL.x); fma2(acc[3][0][1], a3, bL.y);
            fma2(acc[3][1][0], a3, bH.x); fma2(acc[3][1][1], a3, bH.y);
        }
        __syncthreads();
    }

    float* base = g_part + sp * (BB * DD);
    #pragma unroll
    for (int r = 0; r < 4; r++) {
        int m = m0 + 4 * ty + r;
        #pragma unroll
        for (int h = 0; h < 2; h++) {
            float2 p0 = up2(acc[r][h][0]);
            float2 p1 = up2(acc[r][h][1]);
            float4 o = make_float4(p0.x, p0.y, p1.x, p1.y);
            *reinterpret_cast<float4*>(&base[m * DD + n0 + 64 * h + 4 * tx]) = o;
        }
    }
}

// ---------------------------------------------------------------------------
// Kernel 3: g_comb = sum of 8 split partials + (b2 + tb).
// ---------------------------------------------------------------------------
__global__ void __launch_bounds__(256) reduce_kernel(
    const float* __restrict__ b2, const float* __restrict__ tb)
{
    int i4 = blockIdx.x * 256 + threadIdx.x;
    int n  = (i4 & 255) * 4;
    const float4* p = reinterpret_cast<const float4*>(g_part);
    const int stride = BB * DD / 4;
    float4 v2 = *reinterpret_cast<const float4*>(b2 + n);
    float4 vt = *reinterpret_cast<const float4*>(tb + n);
    float4 o = make_float4(v2.x + vt.x, v2.y + vt.y, v2.z + vt.z, v2.w + vt.w);
    #pragma unroll
    for (int sp = 0; sp < NSPLIT; sp++) {
        float4 s = p[i4 + sp * stride];
        o.x += s.x; o.y += s.y; o.z += s.z; o.w += s.w;
    }
    reinterpret_cast<float4*>(g_comb)[i4] = o;
}

// ---------------------------------------------------------------------------
// Kernel 4: assembly with SMEM tables.
// Block = (d-slab 128, s-chunk 16, b-chunk 32), 512 threads.
// smem: pemb 64KB + temb 2.5KB + ts/ix 4KB = 70.5KB -> 3 CTAs/SM (48 warps).
// Grid (8 dslab, 8 schunk, 8 bchunk) = 512 blocks.
// ---------------------------------------------------------------------------
#define EMB_SMEM_BYTES (128*32*16 + 5*32*16 + 2*32*16*4)  // 72192

__global__ void __launch_bounds__(512, 3) emb_kernel(
    const int*   __restrict__ types,
    const int*   __restrict__ inds,
    const float* __restrict__ temb,   // [5,1024]
    const float* __restrict__ pemb,   // [128,1024]
    const float* __restrict__ femb,   // [128,1024]
    float*       __restrict__ out)
{
    extern __shared__ char smem[];
    float4* pembS = reinterpret_cast<float4*>(smem);              // [128][32]
    float4* tembS = pembS + 128 * 32;                             // [5][32]
    int*    tsS   = reinterpret_cast<int*>(tembS + 5 * 32);       // [32][16]
    int*    ixS   = tsS + 32 * 16;                                // [32][16]

    const int tid = threadIdx.x;
    const int d4  = tid & 31;
    const int sg  = tid >> 5;                  // warp id = local s (0..15)
    const int dsl = blockIdx.x;
    const int s0  = blockIdx.y * 16;
    const int b0  = blockIdx.z * 32;
    const int d   = dsl * 128 + d4 * 4;
    const int s   = s0 + sg;

    const float4* pemb4 = reinterpret_cast<const float4*>(pemb);
    const float4* temb4 = reinterpret_cast<const float4*>(temb);
    #pragma unroll
    for (int i = tid; i < 128 * 32; i += 512) {
        int row = i >> 5, c = i & 31;
        pembS[i] = pemb4[row * 256 + dsl * 32 + c];
    }
    if (tid < 5 * 32) {
        int row = tid >> 5, c = tid & 31;
        tembS[tid] = temb4[row * 256 + dsl * 32 + c];
    }
    if (tid < 128) {                 // ts: 32b x 16s = 128 int4
        int b_ = tid >> 2, q = (tid & 3) * 4;
        *reinterpret_cast<int4*>(&tsS[b_ * 16 + q]) =
            *reinterpret_cast<const int4*>(&types[(b0 + b_) * SS + s0 + q]);
    } else if (tid < 256) {
        int j = tid - 128;
        int b_ = j >> 2, q = (j & 3) * 4;
        *reinterpret_cast<int4*>(&ixS[b_ * 16 + q]) =
            *reinterpret_cast<const int4*>(&inds[(b0 + b_) * SS + s0 + q]);
    }
    float4 fr = *reinterpret_cast<const float4*>(&femb[s * DD + d]);
    __syncthreads();

    float* obase = out + (size_t)s * DD + d;

    #pragma unroll 4
    for (int bb = 0; bb < 32; bb++) {
        const int b  = b0 + bb;
        const int t  = tsS[bb * 16 + sg];
        const int iv = ixS[bb * 16 + sg];
        float4 pe = pembS[iv * 32 + d4];
        float4 te = tembS[t * 32 + d4];
        float4 v;
        v.x = fr.x + te.x + pe.x;
        v.y = fr.y + te.y + pe.y;
        v.z = fr.z + te.z + pe.z;
        v.w = fr.w + te.w + pe.w;
        if (t == 1) {   // warp-uniform; comb fetched only when needed (L2-hot)
            float4 c = *reinterpret_cast<const float4*>(&g_comb[b * DD + d]);
            v.x += c.x; v.y += c.y; v.z += c.z; v.w += c.w;
        }
        *reinterpret_cast<float4*>(obase + (size_t)b * SS * DD) = v;
    }
}

// ---------------------------------------------------------------------------
extern "C" void kernel_launch(void* const* d_in, const int* in_sizes, int n_in,
                              void* d_out, int out_size)
{
    const int*   types = (const int*)  d_in[0];
    const int*   inds  = (const int*)  d_in[1];
    const float* style = (const float*)d_in[2];
    const float* cap   = (const float*)d_in[3];
    const float* temb  = (const float*)d_in[4];
    const float* pemb  = (const float*)d_in[5];
    const float* w1    = (const float*)d_in[6];
    const float* b1    = (const float*)d_in[7];
    const float* w2    = (const float*)d_in[8];
    const float* b2    = (const float*)d_in[9];
    const float* tw    = (const float*)d_in[10];
    const float* tb    = (const float*)d_in[11];
    const float* femb  = (const float*)d_in[12];
    float*       out   = (float*)d_out;

    const long long emb_elems = (long long)BB * SS * DD;
    const int write_mask = (out_size >= emb_elems + BB * SS) ? 1 : 0;

    cudaFuncSetAttribute(emb_kernel,
                         cudaFuncAttributeMaxDynamicSharedMemorySize,
                         EMB_SMEM_BYTES);

    // 1: hidden + mask
    prep_kernel<<<96, 256>>>(types, style, w1, b1, out + emb_elems, write_mask);

    // 2: split-K FFMA2 SGEMM -> g_part
    gemm_kernel<<<dim3(DD / 128, BB / 64, NSPLIT), 256>>>(cap, w2, tw);

    // 3: partials + bias -> g_comb
    reduce_kernel<<<BB * DD / 4 / 256, 256>>>(b2, tb);

    // 4: assembly with smem tables (512 blocks, 3 CTAs/SM)
    emb_kernel<<<dim3(8, 8, 8), 512, EMB_SMEM_BYTES>>>(
        types, inds, temb, pemb, femb, out);
}

// round 9
// speedup vs baseline: 4.5098x; 1.0365x over previous
#include <cuda_runtime.h>
#include <cstdint>

// Problem constants (fixed shapes)
#define BB    256      // batch
#define SS    128      // sequence
#define DD    1024     // d_model
#define DQ    256      // style hidden
#define TXT   768      // caption dim
#define KTOT  1024     // DQ + TXT (concat GEMM K)
#define NSPLIT 8
#define KSPL  128      // KTOT / NSPLIT (splits 0,1 -> hidden; 2..7 -> captions)

// Device scratch (no allocation allowed)
__device__ float g_h[BB * DQ];                // relu(style@W1+b1)
__device__ float g_part[NSPLIT * BB * DD];    // split-K partials (8 MB)
__device__ float g_comb[BB * DD];             // combined embed (1 MB)

// ---- packed f32x2 helpers (FFMA2 path, sm_103a) -------------------------
__device__ __forceinline__ unsigned long long pk2(float lo, float hi) {
    unsigned long long r;
    asm("mov.b64 %0, {%1, %2};" : "=l"(r) : "f"(lo), "f"(hi));
    return r;
}
__device__ __forceinline__ void fma2(unsigned long long& d,
                                     unsigned long long a, unsigned long long b) {
    asm("fma.rn.f32x2 %0, %1, %2, %0;" : "+l"(d) : "l"(a), "l"(b));
}
__device__ __forceinline__ float2 up2(unsigned long long v) {
    float2 f;
    asm("mov.b64 {%0, %1}, %2;" : "=f"(f.x), "=f"(f.y) : "l"(v));
    return f;
}
// cp.async 16B (cg = L2 only, straight to smem)
__device__ __forceinline__ void cpa16(uint32_t saddr, const void* g) {
    asm volatile("cp.async.cg.shared.global [%0], [%1], 16;"
                 :: "r"(saddr), "l"(g));
}
#define CPA_COMMIT() asm volatile("cp.async.commit_group;")
// L2-only float4 load (protects L1 pemb slab)
__device__ __forceinline__ float4 ldg_cg4(const float* p) {
    float4 v;
    asm volatile("ld.global.cg.v4.f32 {%0,%1,%2,%3}, [%4];"
                 : "=f"(v.x), "=f"(v.y), "=f"(v.z), "=f"(v.w) : "l"(p));
    return v;
}

// ---------------------------------------------------------------------------
// Kernel 1: hidden = relu(style@W1+b1) + padding mask appended after emb.
// ---------------------------------------------------------------------------
__global__ void __launch_bounds__(256) prep_kernel(
    const int*   __restrict__ types,
    const float* __restrict__ style,   // [B,5]
    const float* __restrict__ w1,      // [5,256]
    const float* __restrict__ b1,      // [256]
    float*       __restrict__ out_mask,
    int          write_mask)
{
    int i4 = blockIdx.x * 256 + threadIdx.x;
    if (i4 < BB * DQ / 4) {
        int b  = i4 >> 6;
        int k4 = (i4 & 63) << 2;
        const float* srow = style + b * 5;
        float s0 = srow[0], s1 = srow[1], s2 = srow[2], s3 = srow[3], s4 = srow[4];
        float4 acc = *reinterpret_cast<const float4*>(b1 + k4);
        #define STEP(si, row) { \
            float4 w = *reinterpret_cast<const float4*>(w1 + (row)*DQ + k4); \
            acc.x = fmaf(si, w.x, acc.x); acc.y = fmaf(si, w.y, acc.y); \
            acc.z = fmaf(si, w.z, acc.z); acc.w = fmaf(si, w.w, acc.w); }
        STEP(s0, 0) STEP(s1, 1) STEP(s2, 2) STEP(s3, 3) STEP(s4, 4)
        #undef STEP
        float4 v = make_float4(fmaxf(acc.x, 0.0f), fmaxf(acc.y, 0.0f),
                               fmaxf(acc.z, 0.0f), fmaxf(acc.w, 0.0f));
        *reinterpret_cast<float4*>(&g_h[b * DQ + k4]) = v;
    } else if (write_mask) {
        int m4 = i4 - BB * DQ / 4;
        if (m4 < BB * SS / 4) {
            int4 t = *reinterpret_cast<const int4*>(types + m4 * 4);
            float4 mv = make_float4(t.x == 0 ? 1.0f : 0.0f, t.y == 0 ? 1.0f : 0.0f,
                                    t.z == 0 ? 1.0f : 0.0f, t.w == 0 ? 1.0f : 0.0f);
            *reinterpret_cast<float4*>(out_mask + m4 * 4) = mv;
        }
    }
}

// ---------------------------------------------------------------------------
// Kernel 2: split-K SGEMM, FFMA2, cp.async double-buffered.
// BM=64 BN=128 BK=32, 4m x 8n micro-tile, 256 threads.
// As kept [m][k] (cp.async can't transpose); compute reads A as float4
// along k (k-groups of 4) so the issue mix stays LDS.128-based.
// Grid (8 n, 4 m, 8 split) = 256 blocks.
// ---------------------------------------------------------------------------
__global__ void __launch_bounds__(256) gemm_kernel(
    const float* __restrict__ cap,  // [256,768]
    const float* __restrict__ w2,   // [256,1024]
    const float* __restrict__ tw)   // [768,1024]
{
    __shared__ float  As[2][64][36];    // [stage][m][k+pad] (144B rows, 16B-aligned)
    __shared__ float4 Bs[2][32][32];    // [stage][k][n/4]

    const int tid = threadIdx.x;
    const int n0  = blockIdx.x * 128;
    const int m0  = blockIdx.y * 64;
    const int sp  = blockIdx.z;
    const int ks  = sp * KSPL;
    const float* W     = (sp < 2) ? (w2 + ks * DD) : (tw + (ks - DQ) * DD);
    const float* Abase = (sp < 2) ? (g_h + ks)     : (cap + (ks - DQ));
    const int    Astr  = (sp < 2) ? DQ : TXT;

    const int tx = tid & 15;
    const int ty = tid >> 4;

    const uint32_t sAs = (uint32_t)__cvta_generic_to_shared(&As[0][0][0]);
    const uint32_t sBs = (uint32_t)__cvta_generic_to_shared(&Bs[0][0][0]);
    const uint32_t asStage = 64 * 36 * 4;     // bytes per A stage
    const uint32_t bsStage = 32 * 32 * 16;    // bytes per B stage

    // per-thread load coords (2 A-float4, 4 B-float4)
    const int am0 = tid >> 3, akq = (tid & 7) * 4;
    const int am1 = (tid + 256) >> 3;

    auto load_stage = [&](int st, int k0) {
        uint32_t aB = sAs + st * asStage;
        uint32_t bB = sBs + st * bsStage;
        cpa16(aB + (am0 * 36 + akq) * 4, Abase + (m0 + am0) * Astr + k0 + akq);
        cpa16(aB + (am1 * 36 + akq) * 4, Abase + (m0 + am1) * Astr + k0 + akq);
        #pragma unroll
        for (int i = 0; i < 4; i++) {
            int idx = tid + i * 256;
            int r = idx >> 5, c4 = idx & 31;
            cpa16(bB + (r * 32 + c4) * 16, W + (k0 + r) * DD + n0 + c4 * 4);
        }
        CPA_COMMIT();
    };

    load_stage(0, 0);
    load_stage(1, 32);

    unsigned long long acc[4][2][2] = {};

    #pragma unroll
    for (int it = 0; it < 4; it++) {
        if (it < 3) asm volatile("cp.async.wait_group 1;");
        else        asm volatile("cp.async.wait_group 0;");
        __syncthreads();
        const int st = it & 1;

        #pragma unroll
        for (int kq = 0; kq < 32; kq += 4) {
            float4 am[4];
            #pragma unroll
            for (int r = 0; r < 4; r++)
                am[r] = *reinterpret_cast<const float4*>(&As[st][4 * ty + r][kq]);
            #pragma unroll
            for (int j = 0; j < 4; j++) {
                const int k = kq + j;
                ulonglong2 bL = *reinterpret_cast<const ulonglong2*>(&Bs[st][k][tx]);
                ulonglong2 bH = *reinterpret_cast<const ulonglong2*>(&Bs[st][k][16 + tx]);
                float a0f = (j == 0) ? am[0].x : (j == 1) ? am[0].y : (j == 2) ? am[0].z : am[0].w;
                float a1f = (j == 0) ? am[1].x : (j == 1) ? am[1].y : (j == 2) ? am[1].z : am[1].w;
                float a2f = (j == 0) ? am[2].x : (j == 1) ? am[2].y : (j == 2) ? am[2].z : am[2].w;
                float a3f = (j == 0) ? am[3].x : (j == 1) ? am[3].y : (j == 2) ? am[3].z : am[3].w;
                unsigned long long a0 = pk2(a0f, a0f);
                unsigned long long a1 = pk2(a1f, a1f);
                unsigned long long a2 = pk2(a2f, a2f);
                unsigned long long a3 = pk2(a3f, a3f);
                fma2(acc[0][0][0], a0, bL.x); fma2(acc[0][0][1], a0, bL.y);
                fma2(acc[0][1][0], a0, bH.x); fma2(acc[0][1][1], a0, bH.y);
                fma2(acc[1][0][0], a1, bL.x); fma2(acc[1][0][1], a1, bL.y);
                fma2(acc[1][1][0], a1, bH.x); fma2(acc[1][1][1], a1, bH.y);
                fma2(acc[2][0][0], a2, bL.x); fma2(acc[2][0][1], a2, bL.y);
                fma2(acc[2][1][0], a2, bH.x); fma2(acc[2][1][1], a2, bH.y);
                fma2(acc[3][0][0], a3, bL.x); fma2(acc[3][0][1], a3, bL.y);
                fma2(acc[3][1][0], a3, bH.x); fma2(acc[3][1][1], a3, bH.y);
            }
        }
        __syncthreads();
        if (it + 2 < 4) load_stage(st, (it + 2) * 32);
    }

    float* base = g_part + sp * (BB * DD);
    #pragma unroll
    for (int r = 0; r < 4; r++) {
        int m = m0 + 4 * ty + r;
        #pragma unroll
        for (int h = 0; h < 2; h++) {
            float2 p0 = up2(acc[r][h][0]);
            float2 p1 = up2(acc[r][h][1]);
            float4 o = make_float4(p0.x, p0.y, p1.x, p1.y);
            *reinterpret_cast<float4*>(&base[m * DD + n0 + 64 * h + 4 * tx]) = o;
        }
    }
}

// ---------------------------------------------------------------------------
// Kernel 3: g_comb = sum of 8 split partials + (b2 + tb).
// ---------------------------------------------------------------------------
__global__ void __launch_bounds__(256) reduce_kernel(
    const float* __restrict__ b2, const float* __restrict__ tb)
{
    int i4 = blockIdx.x * 256 + threadIdx.x;
    int n  = (i4 & 255) * 4;
    const float4* p = reinterpret_cast<const float4*>(g_part);
    const int stride = BB * DD / 4;
    float4 v2 = *reinterpret_cast<const float4*>(b2 + n);
    float4 vt = *reinterpret_cast<const float4*>(tb + n);
    float4 o = make_float4(v2.x + vt.x, v2.y + vt.y, v2.z + vt.z, v2.w + vt.w);
    #pragma unroll
    for (int sp = 0; sp < NSPLIT; sp++) {
        float4 s = p[i4 + sp * stride];
        o.x += s.x; o.y += s.y; o.z += s.z; o.w += s.w;
    }
    reinterpret_cast<float4*>(g_comb)[i4] = o;
}

// ---------------------------------------------------------------------------
// Kernel 4: assembly — register-resident ft[5]=femb[s]+temb[k], direct
// LDG.128 pemb gather (L1-cached slab; dsl = slowest grid dim so
// co-resident CTAs share one 64KB slab), comb via ld.global.cg (L2-only).
// t, iv are warp-uniform (warp = fixed s) -> register select, no divergence.
// Block 512 thr, smem 4KB. Grid (bchunk=8, schunk=8, dsl=8) = 512 blocks.
// ---------------------------------------------------------------------------
__global__ void __launch_bounds__(512) emb_kernel(
    const int*   __restrict__ types,
    const int*   __restrict__ inds,
    const float* __restrict__ temb,   // [5,1024]
    const float* __restrict__ pemb,   // [128,1024]
    const float* __restrict__ femb,   // [128,1024]
    float*       __restrict__ out)
{
    __shared__ int tsS[32 * 16];
    __shared__ int ixS[32 * 16];

    const int tid = threadIdx.x;
    const int d4  = tid & 31;
    const int sg  = tid >> 5;                  // warp id = local s (0..15)
    const int b0  = blockIdx.x * 32;
    const int s0  = blockIdx.y * 16;
    const int dsl = blockIdx.z;                // slowest -> slab locality
    const int d   = dsl * 128 + d4 * 4;
    const int s   = s0 + sg;

    if (tid < 128) {
        int b_ = tid >> 2, q = (tid & 3) * 4;
        *reinterpret_cast<int4*>(&tsS[b_ * 16 + q]) =
            *reinterpret_cast<const int4*>(&types[(b0 + b_) * SS + s0 + q]);
    } else if (tid < 256) {
        int j = tid - 128;
        int b_ = j >> 2, q = (j & 3) * 4;
        *reinterpret_cast<int4*>(&ixS[b_ * 16 + q]) =
            *reinterpret_cast<const int4*>(&inds[(b0 + b_) * SS + s0 + q]);
    }

    // ft[k] = femb[s] + temb[k], k=0..4 — registers, loop-invariant
    const float4 fr = *reinterpret_cast<const float4*>(&femb[s * DD + d]);
    float4 ft[5];
    #pragma unroll
    for (int k = 0; k < 5; k++) {
        float4 te = *reinterpret_cast<const float4*>(&temb[k * DD + d]);
        ft[k] = make_float4(fr.x + te.x, fr.y + te.y, fr.z + te.z, fr.w + te.w);
    }
    __syncthreads();

    float* obase = out + (size_t)s * DD + d;

    #pragma unroll 4
    for (int bb = 0; bb < 32; bb++) {
        const int t  = tsS[bb * 16 + sg];     // warp-uniform
        const int iv = ixS[bb * 16 + sg];     // warp-uniform
        const float4 pe = *reinterpret_cast<const float4*>(&pemb[iv * DD + d]);
        float4 base = (t == 0) ? ft[0] : (t == 1) ? ft[1] :
                      (t == 2) ? ft[2] : (t == 3) ? ft[3] : ft[4];
        float4 v = make_float4(base.x + pe.x, base.y + pe.y,
                               base.z + pe.z, base.w + pe.w);
        if (t == 1) {   // warp-uniform; L2-only read protects the L1 slab
            float4 c = ldg_cg4(&g_comb[(b0 + bb) * DD + d]);
            v.x += c.x; v.y += c.y; v.z += c.z; v.w += c.w;
        }
        *reinterpret_cast<float4*>(obase + (size_t)(b0 + bb) * SS * DD) = v;
    }
}

// ---------------------------------------------------------------------------
extern "C" void kernel_launch(void* const* d_in, const int* in_sizes, int n_in,
                              void* d_out, int out_size)
{
    const int*   types = (const int*)  d_in[0];
    const int*   inds  = (const int*)  d_in[1];
    const float* style = (const float*)d_in[2];
    const float* cap   = (const float*)d_in[3];
    const float* temb  = (const float*)d_in[4];
    const float* pemb  = (const float*)d_in[5];
    const float* w1    = (const float*)d_in[6];
    const float* b1    = (const float*)d_in[7];
    const float* w2    = (const float*)d_in[8];
    const float* b2    = (const float*)d_in[9];
    const float* tw    = (const float*)d_in[10];
    const float* tb    = (const float*)d_in[11];
    const float* femb  = (const float*)d_in[12];
    float*       out   = (float*)d_out;

    const long long emb_elems = (long long)BB * SS * DD;
    const int write_mask = (out_size >= emb_elems + BB * SS) ? 1 : 0;

    // 1: hidden + mask
    prep_kernel<<<96, 256>>>(types, style, w1, b1, out + emb_elems, write_mask);

    // 2: split-K FFMA2 SGEMM (cp.async double-buffered) -> g_part
    gemm_kernel<<<dim3(DD / 128, BB / 64, NSPLIT), 256>>>(cap, w2, tw);

    // 3: partials + bias -> g_comb
    reduce_kernel<<<BB * DD / 4 / 256, 256>>>(b2, tb);

    // 4: assembly (register ft-table, direct pemb gather)
    emb_kernel<<<dim3(8, 8, 8), 512>>>(types, inds, temb, pemb, femb, out);
}

// round 11
// speedup vs baseline: 4.5245x; 1.0033x over previous
#include <cuda_runtime.h>
#include <cstdint>

// Problem constants (fixed shapes)
#define BB    256      // batch
#define SS    128      // sequence
#define DD    1024     // d_model
#define DQ    256      // style hidden
#define TXT   768      // caption dim
#define KTOT  1024     // DQ + TXT (concat GEMM K)
#define NSPLIT 8
#define KSPL  128      // KTOT / NSPLIT (splits 0,1 -> hidden; 2..7 -> captions)

// Device scratch (no allocation allowed)
__device__ float g_h[BB * DQ];                // relu(style@W1+b1)
__device__ float g_part[NSPLIT * BB * DD];    // split-K partials (8 MB)
__device__ float g_comb[BB * DD];             // combined embed (1 MB)

// ---- packed f32x2 helpers (sm_103a) -------------------------------------
__device__ __forceinline__ unsigned long long pk2(float lo, float hi) {
    unsigned long long r;
    asm("mov.b64 %0, {%1, %2};" : "=l"(r) : "f"(lo), "f"(hi));
    return r;
}
__device__ __forceinline__ void fma2(unsigned long long& d,
                                     unsigned long long a, unsigned long long b) {
    asm("fma.rn.f32x2 %0, %1, %2, %0;" : "+l"(d) : "l"(a), "l"(b));
}
__device__ __forceinline__ void add2(unsigned long long& d, unsigned long long a) {
    asm("add.rn.f32x2 %0, %0, %1;" : "+l"(d) : "l"(a));
}
__device__ __forceinline__ float2 up2(unsigned long long v) {
    float2 f;
    asm("mov.b64 {%0, %1}, %2;" : "=f"(f.x), "=f"(f.y) : "l"(v));
    return f;
}
// cp.async 16B (cg = L2 only, straight to smem)
__device__ __forceinline__ void cpa16(uint32_t saddr, const void* g) {
    asm volatile("cp.async.cg.shared.global [%0], [%1], 16;"
                 :: "r"(saddr), "l"(g));
}
#define CPA_COMMIT() asm volatile("cp.async.commit_group;")
// L2-only float4 load (protects L1)
__device__ __forceinline__ float4 ldg_cg4(const float* p) {
    float4 v;
    asm volatile("ld.global.cg.v4.f32 {%0,%1,%2,%3}, [%4];"
                 : "=f"(v.x), "=f"(v.y), "=f"(v.z), "=f"(v.w) : "l"(p));
    return v;
}
// streaming (evict-first) float4 store for the big output
__device__ __forceinline__ void stg_cs4(float* p, float4 v) {
    asm volatile("st.global.cs.v4.f32 [%0], {%1,%2,%3,%4};"
                 :: "l"(p), "f"(v.x), "f"(v.y), "f"(v.z), "f"(v.w));
}

// ---------------------------------------------------------------------------
// Kernel 1: hidden = relu(style@W1+b1) + padding mask appended after emb.
// ---------------------------------------------------------------------------
__global__ void __launch_bounds__(256) prep_kernel(
    const int*   __restrict__ types,
    const float* __restrict__ style,   // [B,5]
    const float* __restrict__ w1,      // [5,256]
    const float* __restrict__ b1,      // [256]
    float*       __restrict__ out_mask,
    int          write_mask)
{
    int i4 = blockIdx.x * 256 + threadIdx.x;
    if (i4 < BB * DQ / 4) {
        int b  = i4 >> 6;
        int k4 = (i4 & 63) << 2;
        const float* srow = style + b * 5;
        float s0 = srow[0], s1 = srow[1], s2 = srow[2], s3 = srow[3], s4 = srow[4];
        float4 acc = *reinterpret_cast<const float4*>(b1 + k4);
        #define STEP(si, row) { \
            float4 w = *reinterpret_cast<const float4*>(w1 + (row)*DQ + k4); \
            acc.x = fmaf(si, w.x, acc.x); acc.y = fmaf(si, w.y, acc.y); \
            acc.z = fmaf(si, w.z, acc.z); acc.w = fmaf(si, w.w, acc.w); }
        STEP(s0, 0) STEP(s1, 1) STEP(s2, 2) STEP(s3, 3) STEP(s4, 4)
        #undef STEP
        float4 v = make_float4(fmaxf(acc.x, 0.0f), fmaxf(acc.y, 0.0f),
                               fmaxf(acc.z, 0.0f), fmaxf(acc.w, 0.0f));
        *reinterpret_cast<float4*>(&g_h[b * DQ + k4]) = v;
    } else if (write_mask) {
        int m4 = i4 - BB * DQ / 4;
        if (m4 < BB * SS / 4) {
            int4 t = *reinterpret_cast<const int4*>(types + m4 * 4);
            float4 mv = make_float4(t.x == 0 ? 1.0f : 0.0f, t.y == 0 ? 1.0f : 0.0f,
                                    t.z == 0 ? 1.0f : 0.0f, t.w == 0 ? 1.0f : 0.0f);
            *reinterpret_cast<float4*>(out_mask + m4 * 4) = mv;
        }
    }
}

// ---------------------------------------------------------------------------
// Kernel 2: split-K SGEMM, FFMA2, cp.async double-buffered (unchanged from R8).
// BM=64 BN=128 BK=32, 4m x 8n micro-tile, 256 threads.
// Grid (8 n, 4 m, 8 split) = 256 blocks.
// ---------------------------------------------------------------------------
__global__ void __launch_bounds__(256) gemm_kernel(
    const float* __restrict__ cap,  // [256,768]
    const float* __restrict__ w2,   // [256,1024]
    const float* __restrict__ tw)   // [768,1024]
{
    __shared__ float  As[2][64][36];
    __shared__ float4 Bs[2][32][32];

    const int tid = threadIdx.x;
    const int n0  = blockIdx.x * 128;
    const int m0  = blockIdx.y * 64;
    const int sp  = blockIdx.z;
    const int ks  = sp * KSPL;
    const float* W     = (sp < 2) ? (w2 + ks * DD) : (tw + (ks - DQ) * DD);
    const float* Abase = (sp < 2) ? (g_h + ks)     : (cap + (ks - DQ));
    const int    Astr  = (sp < 2) ? DQ : TXT;

    const int tx = tid & 15;
    const int ty = tid >> 4;

    const uint32_t sAs = (uint32_t)__cvta_generic_to_shared(&As[0][0][0]);
    const uint32_t sBs = (uint32_t)__cvta_generic_to_shared(&Bs[0][0][0]);
    const uint32_t asStage = 64 * 36 * 4;
    const uint32_t bsStage = 32 * 32 * 16;

    const int am0 = tid >> 3, akq = (tid & 7) * 4;
    const int am1 = (tid + 256) >> 3;

    auto load_stage = [&](int st, int k0) {
        uint32_t aB = sAs + st * asStage;
        uint32_t bB = sBs + st * bsStage;
        cpa16(aB + (am0 * 36 + akq) * 4, Abase + (m0 + am0) * Astr + k0 + akq);
        cpa16(aB + (am1 * 36 + akq) * 4, Abase + (m0 + am1) * Astr + k0 + akq);
        #pragma unroll
        for (int i = 0; i < 4; i++) {
            int idx = tid + i * 256;
            int r = idx >> 5, c4 = idx & 31;
            cpa16(bB + (r * 32 + c4) * 16, W + (k0 + r) * DD + n0 + c4 * 4);
        }
        CPA_COMMIT();
    };

    load_stage(0, 0);
    load_stage(1, 32);

    unsigned long long acc[4][2][2] = {};

    #pragma unroll
    for (int it = 0; it < 4; it++) {
        if (it < 3) asm volatile("cp.async.wait_group 1;");
        else        asm volatile("cp.async.wait_group 0;");
        __syncthreads();
        const int st = it & 1;

        #pragma unroll
        for (int kq = 0; kq < 32; kq += 4) {
            float4 am[4];
            #pragma unroll
            for (int r = 0; r < 4; r++)
                am[r] = *reinterpret_cast<const float4*>(&As[st][4 * ty + r][kq]);
            #pragma unroll
            for (int j = 0; j < 4; j++) {
                const int k = kq + j;
                ulonglong2 bL = *reinterpret_cast<const ulonglong2*>(&Bs[st][k][tx]);
                ulonglong2 bH = *reinterpret_cast<const ulonglong2*>(&Bs[st][k][16 + tx]);
                float a0f = (j == 0) ? am[0].x : (j == 1) ? am[0].y : (j == 2) ? am[0].z : am[0].w;
                float a1f = (j == 0) ? am[1].x : (j == 1) ? am[1].y : (j == 2) ? am[1].z : am[1].w;
                float a2f = (j == 0) ? am[2].x : (j == 1) ? am[2].y : (j == 2) ? am[2].z : am[2].w;
                float a3f = (j == 0) ? am[3].x : (j == 1) ? am[3].y : (j == 2) ? am[3].z : am[3].w;
                unsigned long long a0 = pk2(a0f, a0f);
                unsigned long long a1 = pk2(a1f, a1f);
                unsigned long long a2 = pk2(a2f, a2f);
                unsigned long long a3 = pk2(a3f, a3f);
                fma2(acc[0][0][0], a0, bL.x); fma2(acc[0][0][1], a0, bL.y);
                fma2(acc[0][1][0], a0, bH.x); fma2(acc[0][1][1], a0, bH.y);
                fma2(acc[1][0][0], a1, bL.x); fma2(acc[1][0][1], a1, bL.y);
                fma2(acc[1][1][0], a1, bH.x); fma2(acc[1][1][1], a1, bH.y);
                fma2(acc[2][0][0], a2, bL.x); fma2(acc[2][0][1], a2, bL.y);
                fma2(acc[2][1][0], a2, bH.x); fma2(acc[2][1][1], a2, bH.y);
                fma2(acc[3][0][0], a3, bL.x); fma2(acc[3][0][1], a3, bL.y);
                fma2(acc[3][1][0], a3, bH.x); fma2(acc[3][1][1], a3, bH.y);
            }
        }
        __syncthreads();
        if (it + 2 < 4) load_stage(st, (it + 2) * 32);
    }

    float* base = g_part + sp * (BB * DD);
    #pragma unroll
    for (int r = 0; r < 4; r++) {
        int m = m0 + 4 * ty + r;
        #pragma unroll
        for (int h = 0; h < 2; h++) {
            float2 p0 = up2(acc[r][h][0]);
            float2 p1 = up2(acc[r][h][1]);
            float4 o = make_float4(p0.x, p0.y, p1.x, p1.y);
            *reinterpret_cast<float4*>(&base[m * DD + n0 + 64 * h + 4 * tx]) = o;
        }
    }
}

// ---------------------------------------------------------------------------
// Kernel 3: g_comb = sum of 8 split partials + (b2 + tb).
// ---------------------------------------------------------------------------
__global__ void __launch_bounds__(256) reduce_kernel(
    const float* __restrict__ b2, const float* __restrict__ tb)
{
    int i4 = blockIdx.x * 256 + threadIdx.x;
    int n  = (i4 & 255) * 4;
    const float4* p = reinterpret_cast<const float4*>(g_part);
    const int stride = BB * DD / 4;
    float4 v2 = *reinterpret_cast<const float4*>(b2 + n);
    float4 vt = *reinterpret_cast<const float4*>(tb + n);
    float4 o = make_float4(v2.x + vt.x, v2.y + vt.y, v2.z + vt.z, v2.w + vt.w);
    #pragma unroll
    for (int sp = 0; sp < NSPLIT; sp++) {
        float4 s = p[i4 + sp * stride];
        o.x += s.x; o.y += s.y; o.z += s.z; o.w += s.w;
    }
    reinterpret_cast<float4*>(g_comb)[i4] = o;
}

// ---------------------------------------------------------------------------
// Kernel 4: assembly v3 — smem ftS[s][t][d4] table kills the select chain.
//   base = ftS[sg][t][d4]  : one conflict-free LDS.128 (t warp-uniform)
//   v    = base + pemb[iv] : packed add.rn.f32x2
//   +comb when t==1 (warp-uniform, L2-only load)
//   output via st.global.cs (streaming, evict-first)
// smem: ftS 40KB + ts/ix 4KB = 44KB (static). ~32 regs -> 4 CTAs/SM.
// Grid (bchunk=8, schunk=8, dsl=8) = 512 blocks, dsl slowest for L1 slab reuse.
// ---------------------------------------------------------------------------
__global__ void __launch_bounds__(512) emb_kernel(
    const int*   __restrict__ types,
    const int*   __restrict__ inds,
    const float* __restrict__ temb,   // [5,1024]
    const float* __restrict__ pemb,   // [128,1024]
    const float* __restrict__ femb,   // [128,1024]
    float*       __restrict__ out)
{
    __shared__ float4 ftS[16 * 5 * 32];   // [sg][t][d4]  40KB
    __shared__ int    tsS[32 * 16];
    __shared__ int    ixS[32 * 16];

    const int tid = threadIdx.x;
    const int d4  = tid & 31;
    const int sg  = tid >> 5;                  // warp id = local s (0..15)
    const int b0  = blockIdx.x * 32;
    const int s0  = blockIdx.y * 16;
    const int dsl = blockIdx.z;                // slowest -> slab locality
    const int d   = dsl * 128 + d4 * 4;
    const int s   = s0 + sg;

    if (tid < 128) {
        int b_ = tid >> 2, q = (tid & 3) * 4;
        *reinterpret_cast<int4*>(&tsS[b_ * 16 + q]) =
            *reinterpret_cast<const int4*>(&types[(b0 + b_) * SS + s0 + q]);
    } else if (tid < 256) {
        int j = tid - 128;
        int b_ = j >> 2, q = (j & 3) * 4;
        *reinterpret_cast<int4*>(&ixS[b_ * 16 + q]) =
            *reinterpret_cast<const int4*>(&inds[(b0 + b_) * SS + s0 + q]);
    }

    // Build ftS[sg][k][d4] = femb[s] + temb[k]
    {
        const float4 fr = *reinterpret_cast<const float4*>(&femb[s * DD + d]);
        #pragma unroll
        for (int k = 0; k < 5; k++) {
            float4 te = *reinterpret_cast<const float4*>(&temb[k * DD + d]);
            ftS[(sg * 5 + k) * 32 + d4] =
                make_float4(fr.x + te.x, fr.y + te.y, fr.z + te.z, fr.w + te.w);
        }
    }
    __syncthreads();

    const float4* ftW = &ftS[sg * 5 * 32];     // this warp's 5-row table
    float* obase = out + (size_t)s * DD + d;

    #pragma unroll 4
    for (int bb = 0; bb < 32; bb++) {
        const int t  = tsS[bb * 16 + sg];     // warp-uniform broadcast LDS
        const int iv = ixS[bb * 16 + sg];
        ulonglong2 v = *reinterpret_cast<const ulonglong2*>(&ftW[t * 32 + d4]);
        ulonglong2 pe = *reinterpret_cast<const ulonglong2*>(&pemb[iv * DD + d]);
        add2(v.x, pe.x); add2(v.y, pe.y);
        if (t == 1) {   // warp-uniform; L2-only read
            float4 c = ldg_cg4(&g_comb[(b0 + bb) * DD + d]);
            add2(v.x, pk2(c.x, c.y)); add2(v.y, pk2(c.z, c.w));
        }
        float2 lo = up2(v.x), hi = up2(v.y);
        stg_cs4(obase + (size_t)(b0 + bb) * SS * DD,
                make_float4(lo.x, lo.y, hi.x, hi.y));
    }
}

// ---------------------------------------------------------------------------
extern "C" void kernel_launch(void* const* d_in, const int* in_sizes, int n_in,
                              void* d_out, int out_size)
{
    const int*   types = (const int*)  d_in[0];
    const int*   inds  = (const int*)  d_in[1];
    const float* style = (const float*)d_in[2];
    const float* cap   = (const float*)d_in[3];
    const float* temb  = (const float*)d_in[4];
    const float* pemb  = (const float*)d_in[5];
    const float* w1    = (const float*)d_in[6];
    const float* b1    = (const float*)d_in[7];
    const float* w2    = (const float*)d_in[8];
    const float* b2    = (const float*)d_in[9];
    const float* tw    = (const float*)d_in[10];
    const float* tb    = (const float*)d_in[11];
    const float* femb  = (const float*)d_in[12];
    float*       out   = (float*)d_out;

    const long long emb_elems = (long long)BB * SS * DD;
    const int write_mask = (out_size >= emb_elems + BB * SS) ? 1 : 0;

    // 1: hidden + mask
    prep_kernel<<<96, 256>>>(types, style, w1, b1, out + emb_elems, write_mask);

    // 2: split-K FFMA2 SGEMM (cp.async double-buffered) -> g_part
    gemm_kernel<<<dim3(DD / 128, BB / 64, NSPLIT), 256>>>(cap, w2, tw);

    // 3: partials + bias -> g_comb
    reduce_kernel<<<BB * DD / 4 / 256, 256>>>(b2, tb);

    // 4: assembly (smem ft table, packed adds, streaming stores)
    emb_kernel<<<dim3(8, 8, 8), 512>>>(types, inds, temb, pemb, femb, out);
}

// round 12
// speedup vs baseline: 4.5602x; 1.0079x over previous
#include <cuda_runtime.h>
#include <cstdint>

// Problem constants (fixed shapes)
#define BB    256      // batch
#define SS    128      // sequence
#define DD    1024     // d_model
#define DQ    256      // style hidden
#define TXT   768      // caption dim
#define KTOT  1024     // DQ + TXT (concat GEMM K)
#define NSPLIT 8
#define KSPL  128      // KTOT / NSPLIT (splits 0,1 -> hidden; 2..7 -> captions)

// Device scratch (no allocation allowed)
__device__ float g_h[BB * DQ];                // relu(style@W1+b1)
__device__ float g_part[NSPLIT * BB * DD];    // split-K partials (8 MB)
__device__ float g_comb[BB * DD];             // combined embed (1 MB)
__device__ float g_ftab[SS * 5 * DD];         // femb[s]+temb[t] table (2.6 MB)

// ---- packed f32x2 helpers (sm_103a) -------------------------------------
__device__ __forceinline__ unsigned long long pk2(float lo, float hi) {
    unsigned long long r;
    asm("mov.b64 %0, {%1, %2};" : "=l"(r) : "f"(lo), "f"(hi));
    return r;
}
__device__ __forceinline__ void fma2(unsigned long long& d,
                                     unsigned long long a, unsigned long long b) {
    asm("fma.rn.f32x2 %0, %1, %2, %0;" : "+l"(d) : "l"(a), "l"(b));
}
__device__ __forceinline__ void add2(unsigned long long& d, unsigned long long a) {
    asm("add.rn.f32x2 %0, %0, %1;" : "+l"(d) : "l"(a));
}
__device__ __forceinline__ float2 up2(unsigned long long v) {
    float2 f;
    asm("mov.b64 {%0, %1}, %2;" : "=f"(f.x), "=f"(f.y) : "l"(v));
    return f;
}
// cp.async 16B (cg = L2 only, straight to smem)
__device__ __forceinline__ void cpa16(uint32_t saddr, const void* g) {
    asm volatile("cp.async.cg.shared.global [%0], [%1], 16;"
                 :: "r"(saddr), "l"(g));
}
#define CPA_COMMIT() asm volatile("cp.async.commit_group;")
// L2-only float4 load (protects L1)
__device__ __forceinline__ float4 ldg_cg4(const float* p) {
    float4 v;
    asm volatile("ld.global.cg.v4.f32 {%0,%1,%2,%3}, [%4];"
                 : "=f"(v.x), "=f"(v.y), "=f"(v.z), "=f"(v.w) : "l"(p));
    return v;
}
// streaming (evict-first) float4 store for the big output
__device__ __forceinline__ void stg_cs4(float* p, float4 v) {
    asm volatile("st.global.cs.v4.f32 [%0], {%1,%2,%3,%4};"
                 :: "l"(p), "f"(v.x), "f"(v.y), "f"(v.z), "f"(v.w));
}

// ---------------------------------------------------------------------------
// Kernel 1: hidden = relu(style@W1+b1), padding mask, and the ftab
// precompute ftab[(s*5+t)][d] = femb[s][d] + temb[t][d].  All float4.
// Work: 16384 hidden + 8192 mask + 163840 ftab = 188416 float4 -> 736 blocks.
// ---------------------------------------------------------------------------
#define PREP_HID   (BB * DQ / 4)              // 16384
#define PREP_MASK  (BB * SS / 4)              // 8192
#define PREP_FT    (SS * 5 * DD / 4)          // 163840
#define PREP_TOTAL (PREP_HID + PREP_MASK + PREP_FT)

__global__ void __launch_bounds__(256) prep_kernel(
    const int*   __restrict__ types,
    const float* __restrict__ style,   // [B,5]
    const float* __restrict__ w1,      // [5,256]
    const float* __restrict__ b1,      // [256]
    const float* __restrict__ temb,    // [5,1024]
    const float* __restrict__ femb,    // [128,1024]
    float*       __restrict__ out_mask,
    int          write_mask)
{
    int i4 = blockIdx.x * 256 + threadIdx.x;
    if (i4 < PREP_HID) {
        int b  = i4 >> 6;
        int k4 = (i4 & 63) << 2;
        const float* srow = style + b * 5;
        float s0 = srow[0], s1 = srow[1], s2 = srow[2], s3 = srow[3], s4 = srow[4];
        float4 acc = *reinterpret_cast<const float4*>(b1 + k4);
        #define STEP(si, row) { \
            float4 w = *reinterpret_cast<const float4*>(w1 + (row)*DQ + k4); \
            acc.x = fmaf(si, w.x, acc.x); acc.y = fmaf(si, w.y, acc.y); \
            acc.z = fmaf(si, w.z, acc.z); acc.w = fmaf(si, w.w, acc.w); }
        STEP(s0, 0) STEP(s1, 1) STEP(s2, 2) STEP(s3, 3) STEP(s4, 4)
        #undef STEP
        float4 v = make_float4(fmaxf(acc.x, 0.0f), fmaxf(acc.y, 0.0f),
                               fmaxf(acc.z, 0.0f), fmaxf(acc.w, 0.0f));
        *reinterpret_cast<float4*>(&g_h[b * DQ + k4]) = v;
    } else if (i4 < PREP_HID + PREP_MASK) {
        if (write_mask) {
            int m4 = i4 - PREP_HID;
            int4 t = *reinterpret_cast<const int4*>(types + m4 * 4);
            float4 mv = make_float4(t.x == 0 ? 1.0f : 0.0f, t.y == 0 ? 1.0f : 0.0f,
                                    t.z == 0 ? 1.0f : 0.0f, t.w == 0 ? 1.0f : 0.0f);
            *reinterpret_cast<float4*>(out_mask + m4 * 4) = mv;
        }
    } else if (i4 < PREP_TOTAL) {
        int i4f = i4 - (PREP_HID + PREP_MASK);
        int row = i4f >> 8;            // (s*5 + t), 0..639
        int c4  = i4f & 255;           // float4 column
        int s   = row / 5;
        int t   = row - 5 * s;
        const float4* femb4 = reinterpret_cast<const float4*>(femb);
        const float4* temb4 = reinterpret_cast<const float4*>(temb);
        float4 fe = femb4[s * 256 + c4];
        float4 te = temb4[t * 256 + c4];
        reinterpret_cast<float4*>(g_ftab)[row * 256 + c4] =
            make_float4(fe.x + te.x, fe.y + te.y, fe.z + te.z, fe.w + te.w);
    }
}

// ---------------------------------------------------------------------------
// Kernel 2: split-K SGEMM, FFMA2, cp.async double-buffered (unchanged).
// BM=64 BN=128 BK=32, 4m x 8n micro-tile, 256 threads.
// Grid (8 n, 4 m, 8 split) = 256 blocks.
// ---------------------------------------------------------------------------
__global__ void __launch_bounds__(256) gemm_kernel(
    const float* __restrict__ cap,  // [256,768]
    const float* __restrict__ w2,   // [256,1024]
    const float* __restrict__ tw)   // [768,1024]
{
    __shared__ float  As[2][64][36];
    __shared__ float4 Bs[2][32][32];

    const int tid = threadIdx.x;
    const int n0  = blockIdx.x * 128;
    const int m0  = blockIdx.y * 64;
    const int sp  = blockIdx.z;
    const int ks  = sp * KSPL;
    const float* W     = (sp < 2) ? (w2 + ks * DD) : (tw + (ks - DQ) * DD);
    const float* Abase = (sp < 2) ? (g_h + ks)     : (cap + (ks - DQ));
    const int    Astr  = (sp < 2) ? DQ : TXT;

    const int tx = tid & 15;
    const int ty = tid >> 4;

    const uint32_t sAs = (uint32_t)__cvta_generic_to_shared(&As[0][0][0]);
    const uint32_t sBs = (uint32_t)__cvta_generic_to_shared(&Bs[0][0][0]);
    const uint32_t asStage = 64 * 36 * 4;
    const uint32_t bsStage = 32 * 32 * 16;

    const int am0 = tid >> 3, akq = (tid & 7) * 4;
    const int am1 = (tid + 256) >> 3;

    auto load_stage = [&](int st, int k0) {
        uint32_t aB = sAs + st * asStage;
        uint32_t bB = sBs + st * bsStage;
        cpa16(aB + (am0 * 36 + akq) * 4, Abase + (m0 + am0) * Astr + k0 + akq);
        cpa16(aB + (am1 * 36 + akq) * 4, Abase + (m0 + am1) * Astr + k0 + akq);
        #pragma unroll
        for (int i = 0; i < 4; i++) {
            int idx = tid + i * 256;
            int r = idx >> 5, c4 = idx & 31;
            cpa16(bB + (r * 32 + c4) * 16, W + (k0 + r) * DD + n0 + c4 * 4);
        }
        CPA_COMMIT();
    };

    load_stage(0, 0);
    load_stage(1, 32);

    unsigned long long acc[4][2][2] = {};

    #pragma unroll
    for (int it = 0; it < 4; it++) {
        if (it < 3) asm volatile("cp.async.wait_group 1;");
        else        asm volatile("cp.async.wait_group 0;");
        __syncthreads();
        const int st = it & 1;

        #pragma unroll
        for (int kq = 0; kq < 32; kq += 4) {
            float4 am[4];
            #pragma unroll
            for (int r = 0; r < 4; r++)
                am[r] = *reinterpret_cast<const float4*>(&As[st][4 * ty + r][kq]);
            #pragma unroll
            for (int j = 0; j < 4; j++) {
                const int k = kq + j;
                ulonglong2 bL = *reinterpret_cast<const ulonglong2*>(&Bs[st][k][tx]);
                ulonglong2 bH = *reinterpret_cast<const ulonglong2*>(&Bs[st][k][16 + tx]);
                float a0f = (j == 0) ? am[0].x : (j == 1) ? am[0].y : (j == 2) ? am[0].z : am[0].w;
                float a1f = (j == 0) ? am[1].x : (j == 1) ? am[1].y : (j == 2) ? am[1].z : am[1].w;
                float a2f = (j == 0) ? am[2].x : (j == 1) ? am[2].y : (j == 2) ? am[2].z : am[2].w;
                float a3f = (j == 0) ? am[3].x : (j == 1) ? am[3].y : (j == 2) ? am[3].z : am[3].w;
                unsigned long long a0 = pk2(a0f, a0f);
                unsigned long long a1 = pk2(a1f, a1f);
                unsigned long long a2 = pk2(a2f, a2f);
                unsigned long long a3 = pk2(a3f, a3f);
                fma2(acc[0][0][0], a0, bL.x); fma2(acc[0][0][1], a0, bL.y);
                fma2(acc[0][1][0], a0, bH.x); fma2(acc[0][1][1], a0, bH.y);
                fma2(acc[1][0][0], a1, bL.x); fma2(acc[1][0][1], a1, bL.y);
                fma2(acc[1][1][0], a1, bH.x); fma2(acc[1][1][1], a1, bH.y);
                fma2(acc[2][0][0], a2, bL.x); fma2(acc[2][0][1], a2, bL.y);
                fma2(acc[2][1][0], a2, bH.x); fma2(acc[2][1][1], a2, bH.y);
                fma2(acc[3][0][0], a3, bL.x); fma2(acc[3][0][1], a3, bL.y);
                fma2(acc[3][1][0], a3, bH.x); fma2(acc[3][1][1], a3, bH.y);
            }
        }
        __syncthreads();
        if (it + 2 < 4) load_stage(st, (it + 2) * 32);
    }

    float* base = g_part + sp * (BB * DD);
    #pragma unroll
    for (int r = 0; r < 4; r++) {
        int m = m0 + 4 * ty + r;
        #pragma unroll
        for (int h = 0; h < 2; h++) {
            float2 p0 = up2(acc[r][h][0]);
            float2 p1 = up2(acc[r][h][1]);
            float4 o = make_float4(p0.x, p0.y, p1.x, p1.y);
            *reinterpret_cast<float4*>(&base[m * DD + n0 + 64 * h + 4 * tx]) = o;
        }
    }
}

// ---------------------------------------------------------------------------
// Kernel 3: g_comb = sum of 8 split partials + (b2 + tb).
// ---------------------------------------------------------------------------
__global__ void __launch_bounds__(256) reduce_kernel(
    const float* __restrict__ b2, const float* __restrict__ tb)
{
    int i4 = blockIdx.x * 256 + threadIdx.x;
    int n  = (i4 & 255) * 4;
    const float4* p = reinterpret_cast<const float4*>(g_part);
    const int stride = BB * DD / 4;
    float4 v2 = *reinterpret_cast<const float4*>(b2 + n);
    float4 vt = *reinterpret_cast<const float4*>(tb + n);
    float4 o = make_float4(v2.x + vt.x, v2.y + vt.y, v2.z + vt.z, v2.w + vt.w);
    #pragma unroll
    for (int sp = 0; sp < NSPLIT; sp++) {
        float4 s = p[i4 + sp * stride];
        o.x += s.x; o.y += s.y; o.z += s.z; o.w += s.w;
    }
    reinterpret_cast<float4*>(g_comb)[i4] = o;
}

// ---------------------------------------------------------------------------
// Kernel 4: assembly v4 — precomputed ftab kills both the select chain AND
// the smem table.  Per element: LDG.128 ftab (L1-hit) + LDG.128 pemb (L1-hit)
// + packed adds + STG.cs.  No select logic, 4KB smem, ~30 regs -> ~full occ.
// Co-resident CTAs (bchunk fastest) share the 40KB ftab slice + 64KB pemb
// slab -> 104KB L1-resident working set.
// Grid (bchunk=8, schunk=8, dsl=8) = 512 blocks, 512 threads.
// ---------------------------------------------------------------------------
__global__ void __launch_bounds__(512) emb_kernel(
    const int*   __restrict__ types,
    const int*   __restrict__ inds,
    const float* __restrict__ pemb,   // [128,1024]
    float*       __restrict__ out)
{
    __shared__ int tsS[32 * 16];
    __shared__ int ixS[32 * 16];

    const int tid = threadIdx.x;
    const int d4  = tid & 31;
    const int sg  = tid >> 5;                  // warp id = local s (0..15)
    const int b0  = blockIdx.x * 32;
    const int s0  = blockIdx.y * 16;
    const int dsl = blockIdx.z;                // slowest -> slab locality
    const int d   = dsl * 128 + d4 * 4;
    const int s   = s0 + sg;

    if (tid < 128) {
        int b_ = tid >> 2, q = (tid & 3) * 4;
        *reinterpret_cast<int4*>(&tsS[b_ * 16 + q]) =
            *reinterpret_cast<const int4*>(&types[(b0 + b_) * SS + s0 + q]);
    } else if (tid < 256) {
        int j = tid - 128;
        int b_ = j >> 2, q = (j & 3) * 4;
        *reinterpret_cast<int4*>(&ixS[b_ * 16 + q]) =
            *reinterpret_cast<const int4*>(&inds[(b0 + b_) * SS + s0 + q]);
    }
    __syncthreads();

    const float* ftb   = g_ftab + (s * 5) * DD + d;  // + t*DD per iteration
    const float* peb   = pemb + d;                   // + iv*DD
    float*       obase = out + (size_t)s * DD + d;

    #pragma unroll 4
    for (int bb = 0; bb < 32; bb++) {
        const int t  = tsS[bb * 16 + sg];     // warp-uniform broadcast LDS
        const int iv = ixS[bb * 16 + sg];
        ulonglong2 v  = *reinterpret_cast<const ulonglong2*>(ftb + t * DD);
        ulonglong2 pe = *reinterpret_cast<const ulonglong2*>(peb + iv * DD);
        add2(v.x, pe.x); add2(v.y, pe.y);
        if (t == 1) {   // warp-uniform; L2-only read
            float4 c = ldg_cg4(&g_comb[(b0 + bb) * DD + d]);
            add2(v.x, pk2(c.x, c.y)); add2(v.y, pk2(c.z, c.w));
        }
        float2 lo = up2(v.x), hi = up2(v.y);
        stg_cs4(obase + (size_t)(b0 + bb) * SS * DD,
                make_float4(lo.x, lo.y, hi.x, hi.y));
    }
}

// ---------------------------------------------------------------------------
extern "C" void kernel_launch(void* const* d_in, const int* in_sizes, int n_in,
                              void* d_out, int out_size)
{
    const int*   types = (const int*)  d_in[0];
    const int*   inds  = (const int*)  d_in[1];
    const float* style = (const float*)d_in[2];
    const float* cap   = (const float*)d_in[3];
    const float* temb  = (const float*)d_in[4];
    const float* pemb  = (const float*)d_in[5];
    const float* w1    = (const float*)d_in[6];
    const float* b1    = (const float*)d_in[7];
    const float* w2    = (const float*)d_in[8];
    const float* b2    = (const float*)d_in[9];
    const float* tw    = (const float*)d_in[10];
    const float* tb    = (const float*)d_in[11];
    const float* femb  = (const float*)d_in[12];
    float*       out   = (float*)d_out;

    const long long emb_elems = (long long)BB * SS * DD;
    const int write_mask = (out_size >= emb_elems + BB * SS) ? 1 : 0;

    // 1: hidden + mask + ftab precompute
    prep_kernel<<<(PREP_TOTAL + 255) / 256, 256>>>(
        types, style, w1, b1, temb, femb, out + emb_elems, write_mask);

    // 2: split-K FFMA2 SGEMM (cp.async double-buffered) -> g_part
    gemm_kernel<<<dim3(DD / 128, BB / 64, NSPLIT), 256>>>(cap, w2, tw);

    // 3: partials + bias -> g_comb
    reduce_kernel<<<BB * DD / 4 / 256, 256>>>(b2, tb);

    // 4: assembly (ftab + pemb, both L1-resident; streaming stores)
    emb_kernel<<<dim3(8, 8, 8), 512>>>(types, inds, pemb, out);
}

// round 14
// speedup vs baseline: 4.9163x; 1.0781x over previous
#include <cuda_runtime.h>
#include <cstdint>

// Problem constants (fixed shapes)
#define BB    256      // batch
#define SS    128      // sequence
#define DD    1024     // d_model
#define DQ    256      // style hidden
#define TXT   768      // caption dim
#define KTOT  1024     // DQ + TXT (concat GEMM K)
#define NSPLIT 8
#define KSPL  128      // KTOT / NSPLIT (splits 0,1 -> hidden; 2..7 -> captions)

// Device scratch (no allocation allowed)
__device__ float g_h[BB * DQ];                // relu(style@W1+b1)
__device__ float g_part[NSPLIT * BB * DD];    // split-K partials (8 MB)
__device__ float g_comb[BB * DD];             // combined embed (1 MB)
__device__ float g_ftab[SS * 5 * DD];         // femb[s]+temb[t] table (2.6 MB)

// ---- packed f32x2 helpers (sm_103a) -------------------------------------
__device__ __forceinline__ unsigned long long pk2(float lo, float hi) {
    unsigned long long r;
    asm("mov.b64 %0, {%1, %2};" : "=l"(r) : "f"(lo), "f"(hi));
    return r;
}
__device__ __forceinline__ void fma2(unsigned long long& d,
                                     unsigned long long a, unsigned long long b) {
    asm("fma.rn.f32x2 %0, %1, %2, %0;" : "+l"(d) : "l"(a), "l"(b));
}
__device__ __forceinline__ void add2(unsigned long long& d, unsigned long long a) {
    asm("add.rn.f32x2 %0, %0, %1;" : "+l"(d) : "l"(a));
}
__device__ __forceinline__ float2 up2(unsigned long long v) {
    float2 f;
    asm("mov.b64 {%0, %1}, %2;" : "=f"(f.x), "=f"(f.y) : "l"(v));
    return f;
}
// cp.async 16B (cg = L2 only, straight to smem)
__device__ __forceinline__ void cpa16(uint32_t saddr, const void* g) {
    asm volatile("cp.async.cg.shared.global [%0], [%1], 16;"
                 :: "r"(saddr), "l"(g));
}
#define CPA_COMMIT() asm volatile("cp.async.commit_group;")
// streaming (evict-first) float4 store for the big output
__device__ __forceinline__ void stg_cs4(float* p, float4 v) {
    asm volatile("st.global.cs.v4.f32 [%0], {%1,%2,%3,%4};"
                 :: "l"(p), "f"(v.x), "f"(v.y), "f"(v.z), "f"(v.w));
}

// ---------------------------------------------------------------------------
// Kernel 1: hidden = relu(style@W1+b1), padding mask, and
// ftab[(s*5+t)][d] = femb[s][d] + temb[t][d].  All float4.
// ---------------------------------------------------------------------------
#define PREP_HID   (BB * DQ / 4)              // 16384
#define PREP_MASK  (BB * SS / 4)              // 8192
#define PREP_FT    (SS * 5 * DD / 4)          // 163840
#define PREP_TOTAL (PREP_HID + PREP_MASK + PREP_FT)

__global__ void __launch_bounds__(256) prep_kernel(
    const int*   __restrict__ types,
    const float* __restrict__ style,   // [B,5]
    const float* __restrict__ w1,      // [5,256]
    const float* __restrict__ b1,      // [256]
    const float* __restrict__ temb,    // [5,1024]
    const float* __restrict__ femb,    // [128,1024]
    float*       __restrict__ out_mask,
    int          write_mask)
{
    int i4 = blockIdx.x * 256 + threadIdx.x;
    if (i4 < PREP_HID) {
        int b  = i4 >> 6;
        int k4 = (i4 & 63) << 2;
        const float* srow = style + b * 5;
        float s0 = srow[0], s1 = srow[1], s2 = srow[2], s3 = srow[3], s4 = srow[4];
        float4 acc = *reinterpret_cast<const float4*>(b1 + k4);
        #define STEP(si, row) { \
            float4 w = *reinterpret_cast<const float4*>(w1 + (row)*DQ + k4); \
            acc.x = fmaf(si, w.x, acc.x); acc.y = fmaf(si, w.y, acc.y); \
            acc.z = fmaf(si, w.z, acc.z); acc.w = fmaf(si, w.w, acc.w); }
        STEP(s0, 0) STEP(s1, 1) STEP(s2, 2) STEP(s3, 3) STEP(s4, 4)
        #undef STEP
        float4 v = make_float4(fmaxf(acc.x, 0.0f), fmaxf(acc.y, 0.0f),
                               fmaxf(acc.z, 0.0f), fmaxf(acc.w, 0.0f));
        *reinterpret_cast<float4*>(&g_h[b * DQ + k4]) = v;
    } else if (i4 < PREP_HID + PREP_MASK) {
        if (write_mask) {
            int m4 = i4 - PREP_HID;
            int4 t = *reinterpret_cast<const int4*>(types + m4 * 4);
            float4 mv = make_float4(t.x == 0 ? 1.0f : 0.0f, t.y == 0 ? 1.0f : 0.0f,
                                    t.z == 0 ? 1.0f : 0.0f, t.w == 0 ? 1.0f : 0.0f);
            *reinterpret_cast<float4*>(out_mask + m4 * 4) = mv;
        }
    } else if (i4 < PREP_TOTAL) {
        int i4f = i4 - (PREP_HID + PREP_MASK);
        int row = i4f >> 8;            // (s*5 + t), 0..639
        int c4  = i4f & 255;           // float4 column
        int s   = row / 5;
        int t   = row - 5 * s;
        const float4* femb4 = reinterpret_cast<const float4*>(femb);
        const float4* temb4 = reinterpret_cast<const float4*>(temb);
        float4 fe = femb4[s * 256 + c4];
        float4 te = temb4[t * 256 + c4];
        reinterpret_cast<float4*>(g_ftab)[row * 256 + c4] =
            make_float4(fe.x + te.x, fe.y + te.y, fe.z + te.z, fe.w + te.w);
    }
}

// ---------------------------------------------------------------------------
// Kernel 2: split-K SGEMM, FFMA2, cp.async double-buffered (unchanged).
// BM=64 BN=128 BK=32, 4m x 8n micro-tile, 256 threads.
// Grid (8 n, 4 m, 8 split) = 256 blocks.
// ---------------------------------------------------------------------------
__global__ void __launch_bounds__(256) gemm_kernel(
    const float* __restrict__ cap,  // [256,768]
    const float* __restrict__ w2,   // [256,1024]
    const float* __restrict__ tw)   // [768,1024]
{
    __shared__ float  As[2][64][36];
    __shared__ float4 Bs[2][32][32];

    const int tid = threadIdx.x;
    const int n0  = blockIdx.x * 128;
    const int m0  = blockIdx.y * 64;
    const int sp  = blockIdx.z;
    const int ks  = sp * KSPL;
    const float* W     = (sp < 2) ? (w2 + ks * DD) : (tw + (ks - DQ) * DD);
    const float* Abase = (sp < 2) ? (g_h + ks)     : (cap + (ks - DQ));
    const int    Astr  = (sp < 2) ? DQ : TXT;

    const int tx = tid & 15;
    const int ty = tid >> 4;

    const uint32_t sAs = (uint32_t)__cvta_generic_to_shared(&As[0][0][0]);
    const uint32_t sBs = (uint32_t)__cvta_generic_to_shared(&Bs[0][0][0]);
    const uint32_t asStage = 64 * 36 * 4;
    const uint32_t bsStage = 32 * 32 * 16;

    const int am0 = tid >> 3, akq = (tid & 7) * 4;
    const int am1 = (tid + 256) >> 3;

    auto load_stage = [&](int st, int k0) {
        uint32_t aB = sAs + st * asStage;
        uint32_t bB = sBs + st * bsStage;
        cpa16(aB + (am0 * 36 + akq) * 4, Abase + (m0 + am0) * Astr + k0 + akq);
        cpa16(aB + (am1 * 36 + akq) * 4, Abase + (m0 + am1) * Astr + k0 + akq);
        #pragma unroll
        for (int i = 0; i < 4; i++) {
            int idx = tid + i * 256;
            int r = idx >> 5, c4 = idx & 31;
            cpa16(bB + (r * 32 + c4) * 16, W + (k0 + r) * DD + n0 + c4 * 4);
        }
        CPA_COMMIT();
    };

    load_stage(0, 0);
    load_stage(1, 32);

    unsigned long long acc[4][2][2] = {};

    #pragma unroll
    for (int it = 0; it < 4; it++) {
        if (it < 3) asm volatile("cp.async.wait_group 1;");
        else        asm volatile("cp.async.wait_group 0;");
        __syncthreads();
        const int st = it & 1;

        #pragma unroll
        for (int kq = 0; kq < 32; kq += 4) {
            float4 am[4];
            #pragma unroll
            for (int r = 0; r < 4; r++)
                am[r] = *reinterpret_cast<const float4*>(&As[st][4 * ty + r][kq]);
            #pragma unroll
            for (int j = 0; j < 4; j++) {
                const int k = kq + j;
                ulonglong2 bL = *reinterpret_cast<const ulonglong2*>(&Bs[st][k][tx]);
                ulonglong2 bH = *reinterpret_cast<const ulonglong2*>(&Bs[st][k][16 + tx]);
                float a0f = (j == 0) ? am[0].x : (j == 1) ? am[0].y : (j == 2) ? am[0].z : am[0].w;
                float a1f = (j == 0) ? am[1].x : (j == 1) ? am[1].y : (j == 2) ? am[1].z : am[1].w;
                float a2f = (j == 0) ? am[2].x : (j == 1) ? am[2].y : (j == 2) ? am[2].z : am[2].w;
                float a3f = (j == 0) ? am[3].x : (j == 1) ? am[3].y : (j == 2) ? am[3].z : am[3].w;
                unsigned long long a0 = pk2(a0f, a0f);
                unsigned long long a1 = pk2(a1f, a1f);
                unsigned long long a2 = pk2(a2f, a2f);
                unsigned long long a3 = pk2(a3f, a3f);
                fma2(acc[0][0][0], a0, bL.x); fma2(acc[0][0][1], a0, bL.y);
                fma2(acc[0][1][0], a0, bH.x); fma2(acc[0][1][1], a0, bH.y);
                fma2(acc[1][0][0], a1, bL.x); fma2(acc[1][0][1], a1, bL.y);
                fma2(acc[1][1][0], a1, bH.x); fma2(acc[1][1][1], a1, bH.y);
                fma2(acc[2][0][0], a2, bL.x); fma2(acc[2][0][1], a2, bL.y);
                fma2(acc[2][1][0], a2, bH.x); fma2(acc[2][1][1], a2, bH.y);
                fma2(acc[3][0][0], a3, bL.x); fma2(acc[3][0][1], a3, bL.y);
                fma2(acc[3][1][0], a3, bH.x); fma2(acc[3][1][1], a3, bH.y);
            }
        }
        __syncthreads();
        if (it + 2 < 4) load_stage(st, (it + 2) * 32);
    }

    float* base = g_part + sp * (BB * DD);
    #pragma unroll
    for (int r = 0; r < 4; r++) {
        int m = m0 + 4 * ty + r;
        #pragma unroll
        for (int h = 0; h < 2; h++) {
            float2 p0 = up2(acc[r][h][0]);
            float2 p1 = up2(acc[r][h][1]);
            float4 o = make_float4(p0.x, p0.y, p1.x, p1.y);
            *reinterpret_cast<float4*>(&base[m * DD + n0 + 64 * h + 4 * tx]) = o;
        }
    }
}

// ---------------------------------------------------------------------------
// Kernel 3: g_comb = sum of 8 split partials + (b2 + tb).
// ---------------------------------------------------------------------------
__global__ void __launch_bounds__(256) reduce_kernel(
    const float* __restrict__ b2, const float* __restrict__ tb)
{
    int i4 = blockIdx.x * 256 + threadIdx.x;
    int n  = (i4 & 255) * 4;
    const float4* p = reinterpret_cast<const float4*>(g_part);
    const int stride = BB * DD / 4;
    float4 v2 = *reinterpret_cast<const float4*>(b2 + n);
    float4 vt = *reinterpret_cast<const float4*>(tb + n);
    float4 o = make_float4(v2.x + vt.x, v2.y + vt.y, v2.z + vt.z, v2.w + vt.w);
    #pragma unroll
    for (int sp = 0; sp < NSPLIT; sp++) {
        float4 s = p[i4 + sp * stride];
        o.x += s.x; o.y += s.y; o.z += s.z; o.w += s.w;
    }
    reinterpret_cast<float4*>(g_comb)[i4] = o;
}

// ---------------------------------------------------------------------------
// Kernel 5: assembly v5 — warp = fixed b, loop over s.
//   comb[b] loaded ONCE per warp into registers -> the t==1 path is pure
//   register adds (no in-loop long-scoreboard L2 read).
//   t,iv warp-uniform per iteration; ftab/pemb reads coalesced L1-hit LDG.128.
//   Stores walk s with 4KB stride (64KB window per warp) -> better locality.
// Block 512 thr (16 warps = 16 b), loop 16 s, full unroll.
// Grid (bchunk=16, schunk=8, dsl=8) = 1024 blocks, bchunk fastest.
// ---------------------------------------------------------------------------
__global__ void __launch_bounds__(512) emb_kernel(
    const int*   __restrict__ types,
    const int*   __restrict__ inds,
    const float* __restrict__ pemb,   // [128,1024]
    float*       __restrict__ out)
{
    __shared__ int tsS[16 * 16];      // [b][s]
    __shared__ int ixS[16 * 16];

    const int tid = threadIdx.x;
    const int d4  = tid & 31;
    const int wb  = tid >> 5;                  // warp id = local b (0..15)
    const int b0  = blockIdx.x * 16;
    const int s0  = blockIdx.y * 16;
    const int dsl = blockIdx.z;                // slowest -> slab locality
    const int d   = dsl * 128 + d4 * 4;
    const int b   = b0 + wb;

    if (tid < 64) {
        int b_ = tid >> 2, q = (tid & 3) * 4;
        *reinterpret_cast<int4*>(&tsS[b_ * 16 + q]) =
            *reinterpret_cast<const int4*>(&types[(b0 + b_) * SS + s0 + q]);
    } else if (tid < 128) {
        int j = tid - 64;
        int b_ = j >> 2, q = (j & 3) * 4;
        *reinterpret_cast<int4*>(&ixS[b_ * 16 + q]) =
            *reinterpret_cast<const int4*>(&inds[(b0 + b_) * SS + s0 + q]);
    }

    // comb[b] once per warp -> registers (loop-invariant)
    ulonglong2 cmb;
    {
        float4 c = *reinterpret_cast<const float4*>(&g_comb[b * DD + d]);
        cmb.x = pk2(c.x, c.y);
        cmb.y = pk2(c.z, c.w);
    }
    __syncthreads();

    const float* ftb = g_ftab + (size_t)(s0 * 5) * DD + d;  // + (ss*5+t)*DD
    float*     obase = out + ((size_t)b * SS + s0) * DD + d;

    #pragma unroll
    for (int ss = 0; ss < 16; ss++) {
        const int t  = tsS[wb * 16 + ss];     // warp-uniform broadcast LDS
        const int iv = ixS[wb * 16 + ss];
        ulonglong2 v  = *reinterpret_cast<const ulonglong2*>(ftb + (ss * 5 + t) * DD);
        ulonglong2 pe = *reinterpret_cast<const ulonglong2*>(pemb + iv * DD + d);
        add2(v.x, pe.x); add2(v.y, pe.y);
        if (t == 1) {   // warp-uniform; pure register adds now
            add2(v.x, cmb.x); add2(v.y, cmb.y);
        }
        float2 lo = up2(v.x), hi = up2(v.y);
        stg_cs4(obase + ss * DD, make_float4(lo.x, lo.y, hi.x, hi.y));
    }
}

// ---------------------------------------------------------------------------
extern "C" void kernel_launch(void* const* d_in, const int* in_sizes, int n_in,
                              void* d_out, int out_size)
{
    const int*   types = (const int*)  d_in[0];
    const int*   inds  = (const int*)  d_in[1];
    const float* style = (const float*)d_in[2];
    const float* cap   = (const float*)d_in[3];
    const float* temb  = (const float*)d_in[4];
    const float* pemb  = (const float*)d_in[5];
    const float* w1    = (const float*)d_in[6];
    const float* b1    = (const float*)d_in[7];
    const float* w2    = (const float*)d_in[8];
    const float* b2    = (const float*)d_in[9];
    const float* tw    = (const float*)d_in[10];
    const float* tb    = (const float*)d_in[11];
    const float* femb  = (const float*)d_in[12];
    float*       out   = (float*)d_out;

    const long long emb_elems = (long long)BB * SS * DD;
    const int write_mask = (out_size >= emb_elems + BB * SS) ? 1 : 0;

    // 1: hidden + mask + ftab precompute
    prep_kernel<<<(PREP_TOTAL + 255) / 256, 256>>>(
        types, style, w1, b1, temb, femb, out + emb_elems, write_mask);

    // 2: split-K FFMA2 SGEMM (cp.async double-buffered) -> g_part
    gemm_kernel<<<dim3(DD / 128, BB / 64, NSPLIT), 256>>>(cap, w2, tw);

    // 3: partials + bias -> g_comb
    reduce_kernel<<<BB * DD / 4 / 256, 256>>>(b2, tb);

    // 4: assembly (warp = fixed b, comb in registers, s-loop stores)
    emb_kernel<<<dim3(16, 8, 8), 512>>>(types, inds, pemb, out);
}